// round 1
// baseline (speedup 1.0000x reference)
#include <cuda_runtime.h>
#include <math.h>
#include <stdint.h>

// Problem dims (fixed by the reference)
#define Hd   1024
#define Tt   2048
#define Bb   8
#define Pp   64
#define Ee   3
#define RHd  2048
#define BT   (Bb * Tt)      // 16384 tokens
#define C3H  (3 * Hd)       // 3072

// ---------------------------------------------------------------------------
// Scratch (device globals — no runtime allocation allowed)
// ---------------------------------------------------------------------------
__device__ float g_combined[(size_t)BT * C3H];   // [nx | evidence | anchor]
__device__ float g_q[(size_t)BT * Hd];
__device__ float g_k[(size_t)Bb * Pp * Hd];
__device__ float g_v[(size_t)Bb * Pp * Hd];
__device__ float g_h[(size_t)BT * RHd];          // expert hidden (reused per expert)
__device__ float g_routed[(size_t)BT * Hd];
__device__ float g_g1[(size_t)BT * Hd];
__device__ float g_gate[(size_t)BT * Hd];
__device__ float g_probs[(size_t)BT * Ee];

__device__ __forceinline__ float siluf(float x) { return x / (1.0f + expf(-x)); }
__device__ __forceinline__ float sigmf(float x) { return 1.0f / (1.0f + expf(-x)); }

// ---------------------------------------------------------------------------
// LayerNorm + anchor broadcast. One block per token row.
// Writes nx into combined[:, 0:H] and anchor into combined[:, 2H:3H].
// ---------------------------------------------------------------------------
__global__ __launch_bounds__(256)
void ln_anchor_kernel(const float* __restrict__ x,
                      const float* __restrict__ gamma,
                      const float* __restrict__ beta,
                      const float* __restrict__ anchor,
                      float* __restrict__ combined)
{
    const int row = blockIdx.x;          // 0..BT-1
    const int b   = row >> 11;           // T = 2048
    const int tid = threadIdx.x;         // 256 threads
    const float* xr = x + (size_t)row * Hd;

    float v[4];
    float s = 0.f, s2 = 0.f;
#pragma unroll
    for (int i = 0; i < 4; ++i) {
        v[i] = xr[tid + i * 256];
        s  += v[i];
        s2 += v[i] * v[i];
    }
    // block reduce
    __shared__ float red0[8], red1[8];
    const int lane = tid & 31, wid = tid >> 5;
#pragma unroll
    for (int o = 16; o > 0; o >>= 1) {
        s  += __shfl_xor_sync(0xffffffffu, s, o);
        s2 += __shfl_xor_sync(0xffffffffu, s2, o);
    }
    if (lane == 0) { red0[wid] = s; red1[wid] = s2; }
    __syncthreads();
    __shared__ float s_mean, s_rstd;
    if (tid == 0) {
        float ts = 0.f, ts2 = 0.f;
#pragma unroll
        for (int i = 0; i < 8; ++i) { ts += red0[i]; ts2 += red1[i]; }
        float mean = ts * (1.0f / Hd);
        float var  = ts2 * (1.0f / Hd) - mean * mean;
        s_mean = mean;
        s_rstd = rsqrtf(var + 1e-5f);
    }
    __syncthreads();
    const float mean = s_mean, rstd = s_rstd;

    float* crow = combined + (size_t)row * C3H;
    const float* arow = anchor + (size_t)b * Hd;
#pragma unroll
    for (int i = 0; i < 4; ++i) {
        int c = tid + i * 256;
        crow[c]          = (v[i] - mean) * rstd * gamma[c] + beta[c];
        crow[2 * Hd + c] = arow[c];
    }
}

// ---------------------------------------------------------------------------
// Per-token cross-attention over 64 prototypes. One block (128 thr) per token.
// evidence written into combined[:, H:2H].
// ---------------------------------------------------------------------------
__global__ __launch_bounds__(128)
void attn_kernel(const float* __restrict__ q,
                 const float* __restrict__ k,
                 const float* __restrict__ v,
                 float* __restrict__ combined)
{
    const int row = blockIdx.x;
    const int b   = row >> 11;
    const int tid = threadIdx.x;
    const int lane = tid & 31, w = tid >> 5;   // 4 warps

    __shared__ float qs[Hd];
    __shared__ float sc[Pp];

    const float* qr = q + (size_t)row * Hd;
    for (int i = tid; i < Hd; i += 128) qs[i] = qr[i];
    __syncthreads();

    const float* kb = k + (size_t)b * Pp * Hd;
    for (int p = w; p < Pp; p += 4) {
        const float* kr = kb + (size_t)p * Hd;
        float d = 0.f;
        for (int i = lane; i < Hd; i += 32) d += qs[i] * kr[i];
#pragma unroll
        for (int o = 16; o > 0; o >>= 1) d += __shfl_xor_sync(0xffffffffu, d, o);
        if (lane == 0) sc[p] = d * 0.03125f;   // H^-0.5
    }
    __syncthreads();

    // softmax over 64 (warp 0)
    if (w == 0) {
        float a = sc[lane], c = sc[lane + 32];
        float m = fmaxf(a, c);
#pragma unroll
        for (int o = 16; o > 0; o >>= 1) m = fmaxf(m, __shfl_xor_sync(0xffffffffu, m, o));
        float e1 = expf(a - m), e2 = expf(c - m);
        float ssum = e1 + e2;
#pragma unroll
        for (int o = 16; o > 0; o >>= 1) ssum += __shfl_xor_sync(0xffffffffu, ssum, o);
        float inv = 1.0f / ssum;
        sc[lane]      = e1 * inv;
        sc[lane + 32] = e2 * inv;
    }
    __syncthreads();

    // evidence = weights @ v   (each thread owns 8 h-columns)
    const float* vb = v + (size_t)b * Pp * Hd;
    float acc[8];
#pragma unroll
    for (int j = 0; j < 8; ++j) acc[j] = 0.f;
    for (int p = 0; p < Pp; ++p) {
        const float wv = sc[p];
        const float* vr = vb + (size_t)p * Hd;
#pragma unroll
        for (int j = 0; j < 8; ++j) acc[j] += wv * vr[tid + j * 128];
    }
    float* crow = combined + (size_t)row * C3H + Hd;
#pragma unroll
    for (int j = 0; j < 8; ++j) crow[tid + j * 128] = acc[j];
}

// ---------------------------------------------------------------------------
// Router: logits = combined @ W[3072,3] + b, softmax over E=3.
// One block (128 thr) per token; warps 0..2 each compute one logit.
// ---------------------------------------------------------------------------
__global__ __launch_bounds__(128)
void router_kernel(const float* __restrict__ combined,
                   const float* __restrict__ W,
                   const float* __restrict__ bias,
                   float* __restrict__ probs)
{
    const int row = blockIdx.x;
    const int tid = threadIdx.x;
    const int lane = tid & 31, w = tid >> 5;
    __shared__ float lg[Ee];

    if (w < Ee) {
        const float* cr = combined + (size_t)row * C3H;
        float d = 0.f;
        for (int i = lane; i < C3H; i += 32) d += cr[i] * W[(size_t)i * Ee + w];
#pragma unroll
        for (int o = 16; o > 0; o >>= 1) d += __shfl_xor_sync(0xffffffffu, d, o);
        if (lane == 0) lg[w] = d + bias[w];
    }
    __syncthreads();
    if (tid == 0) {
        float m = fmaxf(lg[0], fmaxf(lg[1], lg[2]));
        float e0 = expf(lg[0] - m), e1 = expf(lg[1] - m), e2 = expf(lg[2] - m);
        float inv = 1.0f / (e0 + e1 + e2);
        probs[(size_t)row * Ee + 0] = e0 * inv;
        probs[(size_t)row * Ee + 1] = e1 * inv;
        probs[(size_t)row * Ee + 2] = e2 * inv;
    }
}

// ---------------------------------------------------------------------------
// Generic 128x128x8 fp32 GEMM, 256 threads, 8x8 per-thread tile (split
// quadrants for conflict-free LDS.128). All dims must be multiples of tile.
// Epilogues:
//   0: C = acc
//   1: C = silu(acc + bias)
//   2: C = prob[r]*(acc + bias)           (expert 0, write)
//   3: C += prob[r]*(acc + bias)          (experts 1,2, accumulate)
//   4: C = sigmoid(acc + bias)
//   5: C = resid + gate * (acc + bias)    (final output)
// ---------------------------------------------------------------------------
template<int EPI>
__global__ __launch_bounds__(256)
void gemm128(const float* __restrict__ A, int lda,
             const float* __restrict__ B, int ldb,
             float* __restrict__ C, int ldc, int K,
             const float* __restrict__ bias,
             const float* __restrict__ prob,
             const float* __restrict__ gate,
             const float* __restrict__ resid)
{
    __shared__ float As[8][128];
    __shared__ float Bs[8][128];

    const int bm = blockIdx.y * 128;
    const int bn = blockIdx.x * 128;
    const int tid = threadIdx.x;
    const int a_r = tid >> 1, a_c = (tid & 1) * 4;
    const int b_k = tid >> 5, b_n = (tid & 31) * 4;
    const int tx = tid & 15, ty = tid >> 4;

    const float* Ap = A + (size_t)(bm + a_r) * lda + a_c;
    const float* Bp = B + (size_t)b_k * ldb + bn + b_n;

    float acc[8][8];
#pragma unroll
    for (int i = 0; i < 8; ++i)
#pragma unroll
        for (int j = 0; j < 8; ++j) acc[i][j] = 0.f;

    for (int k0 = 0; k0 < K; k0 += 8) {
        float4 av = *(const float4*)Ap;  Ap += 8;
        float4 bv = *(const float4*)Bp;  Bp += (size_t)8 * ldb;
        As[a_c + 0][a_r] = av.x;
        As[a_c + 1][a_r] = av.y;
        As[a_c + 2][a_r] = av.z;
        As[a_c + 3][a_r] = av.w;
        *(float4*)&Bs[b_k][b_n] = bv;
        __syncthreads();
#pragma unroll
        for (int kk = 0; kk < 8; ++kk) {
            float ar[8], br[8];
            *(float4*)&ar[0] = *(const float4*)&As[kk][ty * 4];
            *(float4*)&ar[4] = *(const float4*)&As[kk][ty * 4 + 64];
            *(float4*)&br[0] = *(const float4*)&Bs[kk][tx * 4];
            *(float4*)&br[4] = *(const float4*)&Bs[kk][tx * 4 + 64];
#pragma unroll
            for (int i = 0; i < 8; ++i)
#pragma unroll
                for (int j = 0; j < 8; ++j)
                    acc[i][j] += ar[i] * br[j];
        }
        __syncthreads();
    }

    // epilogue
#pragma unroll
    for (int i = 0; i < 8; ++i) {
        const int rl = (i < 4) ? (ty * 4 + i) : (64 + ty * 4 + (i - 4));
        const int r = bm + rl;
        float pr = 0.f;
        if (EPI == 2 || EPI == 3) pr = prob[(size_t)r * Ee];
#pragma unroll
        for (int jq = 0; jq < 2; ++jq) {
            const int c = bn + tx * 4 + jq * 64;
            float4 o;
            o.x = acc[i][jq * 4 + 0];
            o.y = acc[i][jq * 4 + 1];
            o.z = acc[i][jq * 4 + 2];
            o.w = acc[i][jq * 4 + 3];
            if (EPI >= 1) {
                float4 bb = *(const float4*)&bias[c];
                o.x += bb.x; o.y += bb.y; o.z += bb.z; o.w += bb.w;
            }
            const size_t off = (size_t)r * ldc + c;
            if (EPI == 1) {
                o.x = siluf(o.x); o.y = siluf(o.y); o.z = siluf(o.z); o.w = siluf(o.w);
            } else if (EPI == 2) {
                o.x *= pr; o.y *= pr; o.z *= pr; o.w *= pr;
            } else if (EPI == 3) {
                float4 old = *(const float4*)&C[off];
                o.x = old.x + pr * o.x; o.y = old.y + pr * o.y;
                o.z = old.z + pr * o.z; o.w = old.w + pr * o.w;
            } else if (EPI == 4) {
                o.x = sigmf(o.x); o.y = sigmf(o.y); o.z = sigmf(o.z); o.w = sigmf(o.w);
            } else if (EPI == 5) {
                float4 gg = *(const float4*)&gate[(size_t)r * ldc + c];
                float4 xx = *(const float4*)&resid[(size_t)r * ldc + c];
                o.x = xx.x + gg.x * o.x; o.y = xx.y + gg.y * o.y;
                o.z = xx.z + gg.z * o.z; o.w = xx.w + gg.w * o.w;
            }
            *(float4*)&C[off] = o;
        }
    }
}

// ---------------------------------------------------------------------------
// Launch
// ---------------------------------------------------------------------------
extern "C" void kernel_launch(void* const* d_in, const int* in_sizes, int n_in,
                              void* d_out, int out_size)
{
    const float* x       = (const float*)d_in[0];
    const float* anchor  = (const float*)d_in[1];
    const float* proto   = (const float*)d_in[2];
    const float* gamma   = (const float*)d_in[3];
    const float* beta    = (const float*)d_in[4];
    const float* Wq      = (const float*)d_in[5];
    const float* Wk      = (const float*)d_in[6];
    const float* Wv      = (const float*)d_in[7];
    const float* routerW = (const float*)d_in[8];
    const float* routerB = (const float*)d_in[9];
    const float* ew1     = (const float*)d_in[10];
    const float* eb1     = (const float*)d_in[11];
    const float* ew2     = (const float*)d_in[12];
    const float* eb2     = (const float*)d_in[13];
    const float* gw1     = (const float*)d_in[14];
    const float* gb1     = (const float*)d_in[15];
    const float* gw2     = (const float*)d_in[16];
    const float* gb2     = (const float*)d_in[17];
    const float* outw    = (const float*)d_in[18];
    const float* outb    = (const float*)d_in[19];
    float* out = (float*)d_out;

    float *combined, *q, *k, *v, *h, *routed, *g1, *gate, *probs;
    cudaGetSymbolAddress((void**)&combined, g_combined);
    cudaGetSymbolAddress((void**)&q,        g_q);
    cudaGetSymbolAddress((void**)&k,        g_k);
    cudaGetSymbolAddress((void**)&v,        g_v);
    cudaGetSymbolAddress((void**)&h,        g_h);
    cudaGetSymbolAddress((void**)&routed,   g_routed);
    cudaGetSymbolAddress((void**)&g1,       g_g1);
    cudaGetSymbolAddress((void**)&gate,     g_gate);
    cudaGetSymbolAddress((void**)&probs,    g_probs);

    // 1) LayerNorm + anchor broadcast into combined
    ln_anchor_kernel<<<BT, 256>>>(x, gamma, beta, anchor, combined);

    // 2) q = nx @ Wq   (A = combined[:,0:H], lda=3H)
    gemm128<0><<<dim3(Hd / 128, BT / 128), 256>>>(
        combined, C3H, Wq, Hd, q, Hd, Hd, nullptr, nullptr, nullptr, nullptr);

    // 3) k/v = proto @ Wk/Wv   (M = B*P = 512)
    gemm128<0><<<dim3(Hd / 128, (Bb * Pp) / 128), 256>>>(
        proto, Hd, Wk, Hd, k, Hd, Hd, nullptr, nullptr, nullptr, nullptr);
    gemm128<0><<<dim3(Hd / 128, (Bb * Pp) / 128), 256>>>(
        proto, Hd, Wv, Hd, v, Hd, Hd, nullptr, nullptr, nullptr, nullptr);

    // 4) attention -> combined[:, H:2H]
    attn_kernel<<<BT, 128>>>(q, k, v, combined);

    // 5) router probs
    router_kernel<<<BT, 128>>>(combined, routerW, routerB, probs);

    // 6) experts
    for (int e = 0; e < Ee; ++e) {
        const float* w1 = ew1 + (size_t)e * C3H * RHd;
        const float* b1 = eb1 + (size_t)e * RHd;
        const float* w2 = ew2 + (size_t)e * RHd * Hd;
        const float* b2 = eb2 + (size_t)e * Hd;
        // h = silu(combined @ w1 + b1)
        gemm128<1><<<dim3(RHd / 128, BT / 128), 256>>>(
            combined, C3H, w1, RHd, h, RHd, C3H, b1, nullptr, nullptr, nullptr);
        // routed {=, +=} prob_e * (h @ w2 + b2)
        if (e == 0)
            gemm128<2><<<dim3(Hd / 128, BT / 128), 256>>>(
                h, RHd, w2, Hd, routed, Hd, RHd, b2, probs + e, nullptr, nullptr);
        else
            gemm128<3><<<dim3(Hd / 128, BT / 128), 256>>>(
                h, RHd, w2, Hd, routed, Hd, RHd, b2, probs + e, nullptr, nullptr);
    }

    // 7) gate MLP
    gemm128<1><<<dim3(Hd / 128, BT / 128), 256>>>(
        combined, C3H, gw1, Hd, g1, Hd, C3H, gb1, nullptr, nullptr, nullptr);
    gemm128<4><<<dim3(Hd / 128, BT / 128), 256>>>(
        g1, Hd, gw2, Hd, gate, Hd, Hd, gb2, nullptr, nullptr, nullptr);

    // 8) out = x + gate * (routed @ outw + outb)
    gemm128<5><<<dim3(Hd / 128, BT / 128), 256>>>(
        routed, Hd, outw, Hd, out, Hd, Hd, outb, nullptr, gate, x);
}

// round 3
// speedup vs baseline: 2.2193x; 2.2193x over previous
#include <cuda_runtime.h>
#include <cuda_bf16.h>
#include <math.h>
#include <stdint.h>

#define Hd   1024
#define Bb   8
#define Pp   64
#define Ee   3
#define RHd  2048
#define BT   16384
#define C3H  3072

// ===========================================================================
// PTX helpers — baseline (sm_80-class) instructions only; no 'a' features.
// ===========================================================================
__device__ __forceinline__ uint32_t smem_u32(const void* p){
    uint32_t a;
    asm("{ .reg .u64 t; cvta.to.shared.u64 t, %1; cvt.u32.u64 %0, t; }" : "=r"(a) : "l"(p));
    return a;
}
#define CPA(dst, src) asm volatile("cp.async.cg.shared.global [%0], [%1], 16;" :: "r"(dst), "l"(src))
#define CPC()  asm volatile("cp.async.commit_group;" ::: "memory")
#define CPW1() asm volatile("cp.async.wait_group 1;" ::: "memory")
#define CPW0() asm volatile("cp.async.wait_group 0;" ::: "memory")

__device__ __forceinline__ void ldsm4(uint32_t* r, uint32_t addr){
    asm volatile("ldmatrix.sync.aligned.m8n8.x4.shared.b16 {%0,%1,%2,%3}, [%4];"
        : "=r"(r[0]), "=r"(r[1]), "=r"(r[2]), "=r"(r[3]) : "r"(addr));
}
__device__ __forceinline__ void mma16816(float* d, const uint32_t* a, const uint32_t* b){
    asm volatile("mma.sync.aligned.m16n8k16.row.col.f32.bf16.bf16.f32 "
        "{%0,%1,%2,%3}, {%4,%5,%6,%7}, {%8,%9}, {%0,%1,%2,%3};"
        : "+f"(d[0]), "+f"(d[1]), "+f"(d[2]), "+f"(d[3])
        : "r"(a[0]), "r"(a[1]), "r"(a[2]), "r"(a[3]), "r"(b[0]), "r"(b[1]));
}

__device__ __forceinline__ void split2(float v, __nv_bfloat16& h, __nv_bfloat16& l){
    h = __float2bfloat16(v);
    l = __float2bfloat16(v - __bfloat162float(h));
}
__device__ __forceinline__ float siluf(float x){ return x / (1.0f + expf(-x)); }
__device__ __forceinline__ float sigmf(float x){ return 1.0f / (1.0f + expf(-x)); }

// ===========================================================================
// Scratch (device globals)
// ===========================================================================
__device__ float g_combined[(size_t)BT * C3H];
__device__ __nv_bfloat16 g_chi[(size_t)BT * C3H];
__device__ __nv_bfloat16 g_clo[(size_t)BT * C3H];
__device__ __nv_bfloat16 g_hhi[(size_t)BT * RHd];
__device__ __nv_bfloat16 g_hlo[(size_t)BT * RHd];
__device__ __nv_bfloat16 g_g1hi[(size_t)BT * Hd];
__device__ __nv_bfloat16 g_g1lo[(size_t)BT * Hd];
__device__ __nv_bfloat16 g_rhi[(size_t)BT * Hd];
__device__ __nv_bfloat16 g_rlo[(size_t)BT * Hd];
__device__ __nv_bfloat16 g_phi[(size_t)Bb * Pp * Hd];
__device__ __nv_bfloat16 g_plo[(size_t)Bb * Pp * Hd];
__device__ float g_q[(size_t)BT * Hd];
__device__ float g_k[(size_t)Bb * Pp * Hd];
__device__ float g_v[(size_t)Bb * Pp * Hd];
__device__ float g_routed[(size_t)BT * Hd];
__device__ float g_gate[(size_t)BT * Hd];
__device__ float g_probs[(size_t)BT * Ee];

#define WQ_OFF   ((size_t)0)
#define WK_OFF   (WQ_OFF  + (size_t)Hd*Hd)
#define WV_OFF   (WK_OFF  + (size_t)Hd*Hd)
#define GW1_OFF  (WV_OFF  + (size_t)Hd*Hd)
#define GW2_OFF  (GW1_OFF + (size_t)C3H*Hd)
#define OW_OFF   (GW2_OFF + (size_t)Hd*Hd)
#define EW1_OFF  (OW_OFF  + (size_t)Hd*Hd)
#define EW2_OFF  (EW1_OFF + (size_t)Ee*C3H*RHd)
#define WT_TOTAL (EW2_OFF + (size_t)Ee*RHd*Hd)
__device__ __nv_bfloat16 g_wT_hi[WT_TOTAL];
__device__ __nv_bfloat16 g_wT_lo[WT_TOTAL];

// ===========================================================================
// Weight transpose + bf16 split: W[K,N] fp32 -> T[N,K] bf16 hi/lo
// ===========================================================================
__global__ __launch_bounds__(256)
void trans_split(const float* __restrict__ W, int K, int N,
                 __nv_bfloat16* __restrict__ Th, __nv_bfloat16* __restrict__ Tl)
{
    __shared__ float t[32][33];
    const int n0 = blockIdx.x * 32, k0 = blockIdx.y * 32;
    const int tx = threadIdx.x & 31, ty = threadIdx.x >> 5;
#pragma unroll
    for (int i = 0; i < 4; ++i)
        t[ty + i * 8][tx] = W[(size_t)(k0 + ty + i * 8) * N + n0 + tx];
    __syncthreads();
#pragma unroll
    for (int i = 0; i < 4; ++i) {
        float v = t[tx][ty + i * 8];
        size_t o = (size_t)(n0 + ty + i * 8) * K + k0 + tx;
        __nv_bfloat16 h, l; split2(v, h, l);
        Th[o] = h; Tl[o] = l;
    }
}

__global__ __launch_bounds__(256)
void split_arr(const float* __restrict__ src, __nv_bfloat16* __restrict__ h,
               __nv_bfloat16* __restrict__ l, int n)
{
    int i = blockIdx.x * 256 + threadIdx.x;
    if (i < n) { __nv_bfloat16 a, b; split2(src[i], a, b); h[i] = a; l[i] = b; }
}

// ===========================================================================
// LayerNorm + anchor broadcast (+ bf16 split into chi/clo)
// ===========================================================================
__global__ __launch_bounds__(256)
void ln_anchor_kernel(const float* __restrict__ x,
                      const float* __restrict__ gamma,
                      const float* __restrict__ beta,
                      const float* __restrict__ anchor,
                      float* __restrict__ combined,
                      __nv_bfloat16* __restrict__ chi,
                      __nv_bfloat16* __restrict__ clo)
{
    const int row = blockIdx.x;
    const int b   = row >> 11;
    const int tid = threadIdx.x;
    const float* xr = x + (size_t)row * Hd;

    float v[4];
    float s = 0.f, s2 = 0.f;
#pragma unroll
    for (int i = 0; i < 4; ++i) {
        v[i] = xr[tid + i * 256];
        s += v[i]; s2 += v[i] * v[i];
    }
    __shared__ float red0[8], red1[8];
    const int lane = tid & 31, wid = tid >> 5;
#pragma unroll
    for (int o = 16; o > 0; o >>= 1) {
        s  += __shfl_xor_sync(0xffffffffu, s, o);
        s2 += __shfl_xor_sync(0xffffffffu, s2, o);
    }
    if (lane == 0) { red0[wid] = s; red1[wid] = s2; }
    __syncthreads();
    __shared__ float s_mean, s_rstd;
    if (tid == 0) {
        float ts = 0.f, ts2 = 0.f;
#pragma unroll
        for (int i = 0; i < 8; ++i) { ts += red0[i]; ts2 += red1[i]; }
        float mean = ts * (1.0f / Hd);
        float var  = ts2 * (1.0f / Hd) - mean * mean;
        s_mean = mean; s_rstd = rsqrtf(var + 1e-5f);
    }
    __syncthreads();
    const float mean = s_mean, rstd = s_rstd;

    float* crow = combined + (size_t)row * C3H;
    __nv_bfloat16* hrow = chi + (size_t)row * C3H;
    __nv_bfloat16* lrow = clo + (size_t)row * C3H;
    const float* arow = anchor + (size_t)b * Hd;
#pragma unroll
    for (int i = 0; i < 4; ++i) {
        int c = tid + i * 256;
        float nx = (v[i] - mean) * rstd * gamma[c] + beta[c];
        float an = arow[c];
        crow[c] = nx;
        crow[2 * Hd + c] = an;
        __nv_bfloat16 h, l;
        split2(nx, h, l); hrow[c] = h; lrow[c] = l;
        split2(an, h, l); hrow[2 * Hd + c] = h; lrow[2 * Hd + c] = l;
    }
}

// ===========================================================================
// Cross-attention, 4 tokens per block
// ===========================================================================
__global__ __launch_bounds__(256)
void attn4_kernel(const float* __restrict__ q,
                  const float* __restrict__ k,
                  const float* __restrict__ v,
                  float* __restrict__ combined,
                  __nv_bfloat16* __restrict__ chi,
                  __nv_bfloat16* __restrict__ clo)
{
    const int t0  = blockIdx.x * 4;
    const int b   = t0 >> 11;
    const int tid = threadIdx.x;
    const int lane = tid & 31, w = tid >> 5;

    __shared__ float qs[4][Hd];
    __shared__ float sc[4][Pp];

#pragma unroll
    for (int i = 0; i < 16; ++i) {
        int idx = tid + i * 256;
        qs[idx >> 10][idx & 1023] = q[(size_t)(t0 + (idx >> 10)) * Hd + (idx & 1023)];
    }
    __syncthreads();

    const float* kb = k + (size_t)b * Pp * Hd;
    for (int p = w; p < Pp; p += 8) {
        const float* kr = kb + (size_t)p * Hd;
        float d0 = 0.f, d1 = 0.f, d2 = 0.f, d3 = 0.f;
        for (int i = lane; i < Hd; i += 32) {
            float kv = kr[i];
            d0 += kv * qs[0][i]; d1 += kv * qs[1][i];
            d2 += kv * qs[2][i]; d3 += kv * qs[3][i];
        }
#pragma unroll
        for (int o = 16; o > 0; o >>= 1) {
            d0 += __shfl_xor_sync(0xffffffffu, d0, o);
            d1 += __shfl_xor_sync(0xffffffffu, d1, o);
            d2 += __shfl_xor_sync(0xffffffffu, d2, o);
            d3 += __shfl_xor_sync(0xffffffffu, d3, o);
        }
        if (lane == 0) {
            sc[0][p] = d0 * 0.03125f; sc[1][p] = d1 * 0.03125f;
            sc[2][p] = d2 * 0.03125f; sc[3][p] = d3 * 0.03125f;
        }
    }
    __syncthreads();

    if (w < 4) {
        float a = sc[w][lane], c = sc[w][lane + 32];
        float m = fmaxf(a, c);
#pragma unroll
        for (int o = 16; o > 0; o >>= 1) m = fmaxf(m, __shfl_xor_sync(0xffffffffu, m, o));
        float e1 = expf(a - m), e2 = expf(c - m);
        float ssum = e1 + e2;
#pragma unroll
        for (int o = 16; o > 0; o >>= 1) ssum += __shfl_xor_sync(0xffffffffu, ssum, o);
        float inv = 1.0f / ssum;
        sc[w][lane] = e1 * inv; sc[w][lane + 32] = e2 * inv;
    }
    __syncthreads();

    const float* vb = v + (size_t)b * Pp * Hd;
    const int c0 = tid * 4;
    float acc[4][4];
#pragma unroll
    for (int t = 0; t < 4; ++t)
#pragma unroll
        for (int j = 0; j < 4; ++j) acc[t][j] = 0.f;
    for (int p = 0; p < Pp; ++p) {
        float4 vv = *(const float4*)(vb + (size_t)p * Hd + c0);
        float w0 = sc[0][p], w1 = sc[1][p], w2 = sc[2][p], w3 = sc[3][p];
        acc[0][0] += w0 * vv.x; acc[0][1] += w0 * vv.y; acc[0][2] += w0 * vv.z; acc[0][3] += w0 * vv.w;
        acc[1][0] += w1 * vv.x; acc[1][1] += w1 * vv.y; acc[1][2] += w1 * vv.z; acc[1][3] += w1 * vv.w;
        acc[2][0] += w2 * vv.x; acc[2][1] += w2 * vv.y; acc[2][2] += w2 * vv.z; acc[2][3] += w2 * vv.w;
        acc[3][0] += w3 * vv.x; acc[3][1] += w3 * vv.y; acc[3][2] += w3 * vv.z; acc[3][3] += w3 * vv.w;
    }
#pragma unroll
    for (int t = 0; t < 4; ++t) {
        size_t base = (size_t)(t0 + t) * C3H + Hd + c0;
#pragma unroll
        for (int j = 0; j < 4; ++j) {
            float e = acc[t][j];
            combined[base + j] = e;
            __nv_bfloat16 h, l; split2(e, h, l);
            chi[base + j] = h; clo[base + j] = l;
        }
    }
}

// ===========================================================================
// Router softmax
// ===========================================================================
__global__ __launch_bounds__(128)
void router_kernel(const float* __restrict__ combined,
                   const float* __restrict__ W,
                   const float* __restrict__ bias,
                   float* __restrict__ probs)
{
    const int row = blockIdx.x;
    const int tid = threadIdx.x;
    const int lane = tid & 31, w = tid >> 5;
    __shared__ float lg[Ee];

    if (w < Ee) {
        const float* cr = combined + (size_t)row * C3H;
        float d = 0.f;
        for (int i = lane; i < C3H; i += 32) d += cr[i] * W[(size_t)i * Ee + w];
#pragma unroll
        for (int o = 16; o > 0; o >>= 1) d += __shfl_xor_sync(0xffffffffu, d, o);
        if (lane == 0) lg[w] = d + bias[w];
    }
    __syncthreads();
    if (tid == 0) {
        float m = fmaxf(lg[0], fmaxf(lg[1], lg[2]));
        float e0 = expf(lg[0] - m), e1 = expf(lg[1] - m), e2 = expf(lg[2] - m);
        float inv = 1.0f / (e0 + e1 + e2);
        probs[(size_t)row * Ee + 0] = e0 * inv;
        probs[(size_t)row * Ee + 1] = e1 * inv;
        probs[(size_t)row * Ee + 2] = e2 * inv;
    }
}

// ===========================================================================
// mma.sync bf16x3 GEMM: C[M,N] = A[M,K](hi+lo) @ B[N,K]^T(hi+lo)
// CTA 128x128, 8 warps (4m x 2n, each 32x64), Ktile=32, 3-stage cp.async.
// SMEM stage: Ahi/Alo/Bhi/Blo, each 128 rows x 80B (64B data + 16B pad).
// EPI: 0 C=acc | 1 silu->hi/lo | 2 prob* store | 3 prob* accum
//      4 accum + hi/lo emit | 5 sigmoid | 6 resid + gate*(..)
// ===========================================================================
#define MAT_SZ   10240            // 128 * 80
#define STG_SZ   40960            // 4 * MAT_SZ
#define SMEM_DYN (3 * STG_SZ)     // 122880

template<int EPI>
__global__ __launch_bounds__(256)
void mma_gemm(const __nv_bfloat16* __restrict__ Ahi, const __nv_bfloat16* __restrict__ Alo, int lda,
              const __nv_bfloat16* __restrict__ Bhi, const __nv_bfloat16* __restrict__ Blo,
              int K,
              float* __restrict__ C, int ldc,
              __nv_bfloat16* __restrict__ Chi, __nv_bfloat16* __restrict__ Clo,
              const float* __restrict__ bias,
              const float* __restrict__ prob,
              const float* __restrict__ gate,
              const float* __restrict__ resid)
{
    extern __shared__ char smem[];
    const uint32_t sb = smem_u32(smem);

    const int tid  = threadIdx.x;
    const int lane = tid & 31, wid = tid >> 5;
    const int bm = blockIdx.y * 128, bn = blockIdx.x * 128;
    const int m0 = (wid >> 1) * 32, n0 = (wid & 1) * 64;

    // ---- per-thread load slots: 2048 16B chunks / iter, 8 per thread ----
    const char* gsrc[8];
    uint32_t    sdst[8];
#pragma unroll
    for (int j = 0; j < 8; ++j) {
        int c   = tid + j * 256;
        int mat = c >> 9;           // 0 Ahi, 1 Alo, 2 Bhi, 3 Blo
        int cc  = c & 511;
        int row = cc >> 2, seg = cc & 3;
        const __nv_bfloat16* base;
        size_t stride; int r0;
        if      (mat == 0) { base = Ahi; stride = lda; r0 = bm + row; }
        else if (mat == 1) { base = Alo; stride = lda; r0 = bm + row; }
        else if (mat == 2) { base = Bhi; stride = K;   r0 = bn + row; }
        else               { base = Blo; stride = K;   r0 = bn + row; }
        gsrc[j] = (const char*)(base + (size_t)r0 * stride + seg * 8);
        sdst[j] = sb + mat * MAT_SZ + row * 80 + seg * 16;
    }

    const int NC = K >> 5;

    // issue(it, stage)
#define ISSUE(it) do{ \
        if ((it) < NC) { \
            uint32_t so_ = ((it) % 3) * STG_SZ; \
            size_t   go_ = (size_t)(it) * 64;   \
            _Pragma("unroll") \
            for (int j = 0; j < 8; ++j) CPA(sdst[j] + so_, gsrc[j] + go_); \
        } \
        CPC(); \
    } while(0)

    ISSUE(0);
    ISSUE(1);

    float acc[2][8][4];
#pragma unroll
    for (int mi = 0; mi < 2; ++mi)
#pragma unroll
        for (int nt = 0; nt < 8; ++nt)
#pragma unroll
            for (int r = 0; r < 4; ++r) acc[mi][nt][r] = 0.f;

    // ldmatrix lane addressing (within stage)
    const uint32_t a_off = (uint32_t)((m0 + (lane & 15)) * 80 + (lane >> 4) * 16);
    const uint32_t b_off = (uint32_t)((n0 + ((lane >> 4) & 1) * 8 + (lane & 7)) * 80
                                      + ((lane >> 3) & 1) * 16);

    for (int it = 0; it < NC; ++it) {
        const uint32_t stg = sb + (it % 3) * STG_SZ;
        CPW1();
        __syncthreads();
        ISSUE(it + 2);

#pragma unroll
        for (int ks = 0; ks < 2; ++ks) {
            uint32_t ah[2][4], al[2][4];
#pragma unroll
            for (int mi = 0; mi < 2; ++mi) {
                uint32_t ad = stg + a_off + mi * (16 * 80) + ks * 32;
                ldsm4(ah[mi], ad);
                ldsm4(al[mi], ad + MAT_SZ);
            }
            uint32_t bh[16], bl[16];
#pragma unroll
            for (int p = 0; p < 4; ++p) {
                uint32_t bd = stg + 2 * MAT_SZ + b_off + p * (16 * 80) + ks * 32;
                ldsm4(bh + p * 4, bd);
                ldsm4(bl + p * 4, bd + MAT_SZ);
            }
#pragma unroll
            for (int mi = 0; mi < 2; ++mi)
#pragma unroll
                for (int nt = 0; nt < 8; ++nt) {
                    mma16816(acc[mi][nt], ah[mi], bh + nt * 2);
                    mma16816(acc[mi][nt], ah[mi], bl + nt * 2);
                    mma16816(acc[mi][nt], al[mi], bh + nt * 2);
                }
        }
    }
    CPW0();

    // ---- epilogue ----
#pragma unroll
    for (int nt = 0; nt < 8; ++nt) {
        const int col = bn + n0 + nt * 8 + (lane & 3) * 2;
        float bia0 = 0.f, bia1 = 0.f;
        if (EPI >= 1) { bia0 = bias[col]; bia1 = bias[col + 1]; }
#pragma unroll
        for (int mi = 0; mi < 2; ++mi) {
#pragma unroll
            for (int hf = 0; hf < 2; ++hf) {
                const int row = bm + m0 + mi * 16 + (lane >> 2) + hf * 8;
                float v0 = acc[mi][nt][hf * 2 + 0];
                float v1 = acc[mi][nt][hf * 2 + 1];
                const size_t off = (size_t)row * ldc + col;
                if (EPI == 0) {
                    *(float2*)(C + off) = make_float2(v0, v1);
                } else if (EPI == 1) {
                    float s0 = siluf(v0 + bia0), s1 = siluf(v1 + bia1);
                    __nv_bfloat16 h0, l0, h1, l1;
                    split2(s0, h0, l0); split2(s1, h1, l1);
                    __nv_bfloat162 hv; hv.x = h0; hv.y = h1;
                    __nv_bfloat162 lv; lv.x = l0; lv.y = l1;
                    *(__nv_bfloat162*)(Chi + off) = hv;
                    *(__nv_bfloat162*)(Clo + off) = lv;
                } else if (EPI == 2) {
                    float p = prob[(size_t)row * Ee];
                    *(float2*)(C + off) = make_float2(p * (v0 + bia0), p * (v1 + bia1));
                } else if (EPI == 3) {
                    float p = prob[(size_t)row * Ee];
                    float2 o = *(const float2*)(C + off);
                    o.x += p * (v0 + bia0); o.y += p * (v1 + bia1);
                    *(float2*)(C + off) = o;
                } else if (EPI == 4) {
                    float p = prob[(size_t)row * Ee];
                    float2 o = *(const float2*)(C + off);
                    float u0 = o.x + p * (v0 + bia0);
                    float u1 = o.y + p * (v1 + bia1);
                    *(float2*)(C + off) = make_float2(u0, u1);
                    __nv_bfloat16 h0, l0, h1, l1;
                    split2(u0, h0, l0); split2(u1, h1, l1);
                    __nv_bfloat162 hv; hv.x = h0; hv.y = h1;
                    __nv_bfloat162 lv; lv.x = l0; lv.y = l1;
                    *(__nv_bfloat162*)(Chi + off) = hv;
                    *(__nv_bfloat162*)(Clo + off) = lv;
                } else if (EPI == 5) {
                    *(float2*)(C + off) = make_float2(sigmf(v0 + bia0), sigmf(v1 + bia1));
                } else {
                    float2 gg = *(const float2*)(gate + off);
                    float2 xx = *(const float2*)(resid + off);
                    *(float2*)(C + off) =
                        make_float2(xx.x + gg.x * (v0 + bia0), xx.y + gg.y * (v1 + bia1));
                }
            }
        }
    }
#undef ISSUE
}

// ===========================================================================
// Launch
// ===========================================================================
extern "C" void kernel_launch(void* const* d_in, const int* in_sizes, int n_in,
                              void* d_out, int out_size)
{
    const float* x       = (const float*)d_in[0];
    const float* anchor  = (const float*)d_in[1];
    const float* proto   = (const float*)d_in[2];
    const float* gamma   = (const float*)d_in[3];
    const float* beta    = (const float*)d_in[4];
    const float* Wq      = (const float*)d_in[5];
    const float* Wk      = (const float*)d_in[6];
    const float* Wv      = (const float*)d_in[7];
    const float* routerW = (const float*)d_in[8];
    const float* routerB = (const float*)d_in[9];
    const float* ew1     = (const float*)d_in[10];
    const float* eb1     = (const float*)d_in[11];
    const float* ew2     = (const float*)d_in[12];
    const float* eb2     = (const float*)d_in[13];
    const float* gw1     = (const float*)d_in[14];
    const float* gb1     = (const float*)d_in[15];
    const float* gw2     = (const float*)d_in[16];
    const float* gb2     = (const float*)d_in[17];
    const float* outw    = (const float*)d_in[18];
    const float* outb    = (const float*)d_in[19];
    float* out = (float*)d_out;

    float *combined, *q, *k, *v, *routed, *gate, *probs;
    __nv_bfloat16 *chi, *clo, *hhi, *hlo, *g1hi, *g1lo, *rhi, *rlo, *phi, *plo, *wth, *wtl;
    cudaGetSymbolAddress((void**)&combined, g_combined);
    cudaGetSymbolAddress((void**)&chi, g_chi);
    cudaGetSymbolAddress((void**)&clo, g_clo);
    cudaGetSymbolAddress((void**)&hhi, g_hhi);
    cudaGetSymbolAddress((void**)&hlo, g_hlo);
    cudaGetSymbolAddress((void**)&g1hi, g_g1hi);
    cudaGetSymbolAddress((void**)&g1lo, g_g1lo);
    cudaGetSymbolAddress((void**)&rhi, g_rhi);
    cudaGetSymbolAddress((void**)&rlo, g_rlo);
    cudaGetSymbolAddress((void**)&phi, g_phi);
    cudaGetSymbolAddress((void**)&plo, g_plo);
    cudaGetSymbolAddress((void**)&q, g_q);
    cudaGetSymbolAddress((void**)&k, g_k);
    cudaGetSymbolAddress((void**)&v, g_v);
    cudaGetSymbolAddress((void**)&routed, g_routed);
    cudaGetSymbolAddress((void**)&gate, g_gate);
    cudaGetSymbolAddress((void**)&probs, g_probs);
    cudaGetSymbolAddress((void**)&wth, g_wT_hi);
    cudaGetSymbolAddress((void**)&wtl, g_wT_lo);

    cudaFuncSetAttribute(mma_gemm<0>, cudaFuncAttributeMaxDynamicSharedMemorySize, SMEM_DYN);
    cudaFuncSetAttribute(mma_gemm<1>, cudaFuncAttributeMaxDynamicSharedMemorySize, SMEM_DYN);
    cudaFuncSetAttribute(mma_gemm<2>, cudaFuncAttributeMaxDynamicSharedMemorySize, SMEM_DYN);
    cudaFuncSetAttribute(mma_gemm<3>, cudaFuncAttributeMaxDynamicSharedMemorySize, SMEM_DYN);
    cudaFuncSetAttribute(mma_gemm<4>, cudaFuncAttributeMaxDynamicSharedMemorySize, SMEM_DYN);
    cudaFuncSetAttribute(mma_gemm<5>, cudaFuncAttributeMaxDynamicSharedMemorySize, SMEM_DYN);
    cudaFuncSetAttribute(mma_gemm<6>, cudaFuncAttributeMaxDynamicSharedMemorySize, SMEM_DYN);

    // ---- weight transposes + splits ----
    trans_split<<<dim3(Hd/32, Hd/32), 256>>>(Wq,   Hd,  Hd,  wth + WQ_OFF,  wtl + WQ_OFF);
    trans_split<<<dim3(Hd/32, Hd/32), 256>>>(Wk,   Hd,  Hd,  wth + WK_OFF,  wtl + WK_OFF);
    trans_split<<<dim3(Hd/32, Hd/32), 256>>>(Wv,   Hd,  Hd,  wth + WV_OFF,  wtl + WV_OFF);
    trans_split<<<dim3(Hd/32, C3H/32), 256>>>(gw1, C3H, Hd,  wth + GW1_OFF, wtl + GW1_OFF);
    trans_split<<<dim3(Hd/32, Hd/32), 256>>>(gw2,  Hd,  Hd,  wth + GW2_OFF, wtl + GW2_OFF);
    trans_split<<<dim3(Hd/32, Hd/32), 256>>>(outw, Hd,  Hd,  wth + OW_OFF,  wtl + OW_OFF);
    for (int e = 0; e < Ee; ++e) {
        trans_split<<<dim3(RHd/32, C3H/32), 256>>>(ew1 + (size_t)e*C3H*RHd, C3H, RHd,
            wth + EW1_OFF + (size_t)e*C3H*RHd, wtl + EW1_OFF + (size_t)e*C3H*RHd);
        trans_split<<<dim3(Hd/32, RHd/32), 256>>>(ew2 + (size_t)e*RHd*Hd, RHd, Hd,
            wth + EW2_OFF + (size_t)e*RHd*Hd, wtl + EW2_OFF + (size_t)e*RHd*Hd);
    }
    split_arr<<<(Bb*Pp*Hd + 255)/256, 256>>>(proto, phi, plo, Bb*Pp*Hd);

    // ---- LN + anchor ----
    ln_anchor_kernel<<<BT, 256>>>(x, gamma, beta, anchor, combined, chi, clo);

    // ---- q, k, v projections ----
    mma_gemm<0><<<dim3(Hd/128, BT/128), 256, SMEM_DYN>>>(
        chi, clo, C3H, wth + WQ_OFF, wtl + WQ_OFF, Hd,
        q, Hd, nullptr, nullptr, nullptr, nullptr, nullptr, nullptr);
    mma_gemm<0><<<dim3(Hd/128, (Bb*Pp)/128), 256, SMEM_DYN>>>(
        phi, plo, Hd, wth + WK_OFF, wtl + WK_OFF, Hd,
        k, Hd, nullptr, nullptr, nullptr, nullptr, nullptr, nullptr);
    mma_gemm<0><<<dim3(Hd/128, (Bb*Pp)/128), 256, SMEM_DYN>>>(
        phi, plo, Hd, wth + WV_OFF, wtl + WV_OFF, Hd,
        v, Hd, nullptr, nullptr, nullptr, nullptr, nullptr, nullptr);

    // ---- attention ----
    attn4_kernel<<<BT/4, 256>>>(q, k, v, combined, chi, clo);

    // ---- router ----
    router_kernel<<<BT, 128>>>(combined, routerW, routerB, probs);

    // ---- experts ----
    for (int e = 0; e < Ee; ++e) {
        const __nv_bfloat16* w1h = wth + EW1_OFF + (size_t)e*C3H*RHd;
        const __nv_bfloat16* w1l = wtl + EW1_OFF + (size_t)e*C3H*RHd;
        const __nv_bfloat16* w2h = wth + EW2_OFF + (size_t)e*RHd*Hd;
        const __nv_bfloat16* w2l = wtl + EW2_OFF + (size_t)e*RHd*Hd;
        const float* b1 = eb1 + (size_t)e * RHd;
        const float* b2 = eb2 + (size_t)e * Hd;
        mma_gemm<1><<<dim3(RHd/128, BT/128), 256, SMEM_DYN>>>(
            chi, clo, C3H, w1h, w1l, C3H,
            nullptr, RHd, hhi, hlo, b1, nullptr, nullptr, nullptr);
        if (e == 0)
            mma_gemm<2><<<dim3(Hd/128, BT/128), 256, SMEM_DYN>>>(
                hhi, hlo, RHd, w2h, w2l, RHd,
                routed, Hd, nullptr, nullptr, b2, probs + e, nullptr, nullptr);
        else if (e == 1)
            mma_gemm<3><<<dim3(Hd/128, BT/128), 256, SMEM_DYN>>>(
                hhi, hlo, RHd, w2h, w2l, RHd,
                routed, Hd, nullptr, nullptr, b2, probs + e, nullptr, nullptr);
        else
            mma_gemm<4><<<dim3(Hd/128, BT/128), 256, SMEM_DYN>>>(
                hhi, hlo, RHd, w2h, w2l, RHd,
                routed, Hd, rhi, rlo, b2, probs + e, nullptr, nullptr);
    }

    // ---- gate MLP ----
    mma_gemm<1><<<dim3(Hd/128, BT/128), 256, SMEM_DYN>>>(
        chi, clo, C3H, wth + GW1_OFF, wtl + GW1_OFF, C3H,
        nullptr, Hd, g1hi, g1lo, gb1, nullptr, nullptr, nullptr);
    mma_gemm<5><<<dim3(Hd/128, BT/128), 256, SMEM_DYN>>>(
        g1hi, g1lo, Hd, wth + GW2_OFF, wtl + GW2_OFF, Hd,
        gate, Hd, nullptr, nullptr, gb2, nullptr, nullptr, nullptr);

    // ---- final ----
    mma_gemm<6><<<dim3(Hd/128, BT/128), 256, SMEM_DYN>>>(
        rhi, rlo, Hd, wth + OW_OFF, wtl + OW_OFF, Hd,
        out, Hd, nullptr, nullptr, outb, nullptr, gate, x);
}

// round 4
// speedup vs baseline: 2.7907x; 1.2575x over previous
#include <cuda_runtime.h>
#include <cuda_bf16.h>
#include <math.h>
#include <stdint.h>

#define Hd   1024
#define Bb   8
#define Pp   64
#define Ee   3
#define RHd  2048
#define BT   16384
#define C2H  2048
#define CK6  6144

// ===========================================================================
// PTX helpers — baseline (sm_80-class) instructions only.
// ===========================================================================
__device__ __forceinline__ uint32_t smem_u32(const void* p){
    uint32_t a;
    asm("{ .reg .u64 t; cvta.to.shared.u64 t, %1; cvt.u32.u64 %0, t; }" : "=r"(a) : "l"(p));
    return a;
}
#define CPA(dst, src) asm volatile("cp.async.cg.shared.global [%0], [%1], 16;" :: "r"(dst), "l"(src))
#define CPC()  asm volatile("cp.async.commit_group;" ::: "memory")
#define CPW1() asm volatile("cp.async.wait_group 1;" ::: "memory")
#define CPW0() asm volatile("cp.async.wait_group 0;" ::: "memory")

__device__ __forceinline__ void ldsm4(uint32_t* r, uint32_t addr){
    asm volatile("ldmatrix.sync.aligned.m8n8.x4.shared.b16 {%0,%1,%2,%3}, [%4];"
        : "=r"(r[0]), "=r"(r[1]), "=r"(r[2]), "=r"(r[3]) : "r"(addr));
}
// non-volatile: pure computation, let the compiler schedule freely
__device__ __forceinline__ void mma16816(float* d, const uint32_t* a, const uint32_t* b){
    asm("mma.sync.aligned.m16n8k16.row.col.f32.bf16.bf16.f32 "
        "{%0,%1,%2,%3}, {%4,%5,%6,%7}, {%8,%9}, {%0,%1,%2,%3};"
        : "+f"(d[0]), "+f"(d[1]), "+f"(d[2]), "+f"(d[3])
        : "r"(a[0]), "r"(a[1]), "r"(a[2]), "r"(a[3]), "r"(b[0]), "r"(b[1]));
}

__device__ __forceinline__ void split2(float v, __nv_bfloat16& h, __nv_bfloat16& l){
    h = __float2bfloat16(v);
    l = __float2bfloat16(v - __bfloat162float(h));
}
__device__ __forceinline__ float siluf(float x){ return x / (1.0f + expf(-x)); }
__device__ __forceinline__ float sigmf(float x){ return 1.0f / (1.0f + expf(-x)); }

// ===========================================================================
// Scratch
// ===========================================================================
__device__ float g_combined[(size_t)BT * C2H];             // [nx | evidence] fp32
__device__ __nv_bfloat16 g_chi[(size_t)BT * C2H];
__device__ __nv_bfloat16 g_clo[(size_t)BT * C2H];
__device__ __nv_bfloat16 g_hhi[(size_t)BT * CK6];          // h' all experts
__device__ __nv_bfloat16 g_hlo[(size_t)BT * CK6];
__device__ __nv_bfloat16 g_g1hi[(size_t)BT * Hd];
__device__ __nv_bfloat16 g_g1lo[(size_t)BT * Hd];
__device__ __nv_bfloat16 g_rhi[(size_t)BT * Hd];
__device__ __nv_bfloat16 g_rlo[(size_t)BT * Hd];
__device__ __nv_bfloat16 g_phi[(size_t)Bb * Pp * Hd];
__device__ __nv_bfloat16 g_plo[(size_t)Bb * Pp * Hd];
__device__ float g_q[(size_t)BT * Hd];
__device__ float g_k[(size_t)Bb * Pp * Hd];
__device__ float g_v[(size_t)Bb * Pp * Hd];
__device__ float g_gate[(size_t)BT * Hd];
__device__ float g_probs[(size_t)BT * Ee];
// anchor-folded terms: aw1[3][8][2048] | ag1[8][1024] | arl[8][3]
__device__ float g_aux[3*8*2048 + 8*1024 + 8*3];
#define AUX_AG1 49152
#define AUX_ARL 57344

// transposed/split weights
#define WQ_OFF   ((size_t)0)
#define WK_OFF   (WQ_OFF  + (size_t)Hd*Hd)
#define WV_OFF   (WK_OFF  + (size_t)Hd*Hd)
#define GW1_OFF  (WV_OFF  + (size_t)Hd*Hd)               // [1024][2048]
#define GW2_OFF  (GW1_OFF + (size_t)Hd*C2H)
#define OW_OFF   (GW2_OFF + (size_t)Hd*Hd)
#define EW1_OFF  (OW_OFF  + (size_t)Hd*Hd)               // 3 x [2048][2048]
#define EW2_OFF  (EW1_OFF + (size_t)Ee*RHd*C2H)          // [1024][6144]
#define WT_TOTAL (EW2_OFF + (size_t)Hd*CK6)
__device__ __nv_bfloat16 g_wT_hi[WT_TOTAL];
__device__ __nv_bfloat16 g_wT_lo[WT_TOTAL];

// ===========================================================================
// Weight transpose + split: W[K?,N] fp32 (rows k0..), T[n][koff+k] bf16 hi/lo
// ===========================================================================
__global__ __launch_bounds__(256)
void trans_split(const float* __restrict__ W, int N,
                 __nv_bfloat16* __restrict__ Th, __nv_bfloat16* __restrict__ Tl,
                 int ldT, int koff)
{
    __shared__ float t[32][33];
    const int n0 = blockIdx.x * 32, k0 = blockIdx.y * 32;
    const int tx = threadIdx.x & 31, ty = threadIdx.x >> 5;
#pragma unroll
    for (int i = 0; i < 4; ++i)
        t[ty + i * 8][tx] = W[(size_t)(k0 + ty + i * 8) * N + n0 + tx];
    __syncthreads();
#pragma unroll
    for (int i = 0; i < 4; ++i) {
        float v = t[tx][ty + i * 8];
        size_t o = (size_t)(n0 + ty + i * 8) * ldT + koff + k0 + tx;
        __nv_bfloat16 h, l; split2(v, h, l);
        Th[o] = h; Tl[o] = l;
    }
}

__global__ __launch_bounds__(256)
void split_arr(const float* __restrict__ src, __nv_bfloat16* __restrict__ h,
               __nv_bfloat16* __restrict__ l, int n)
{
    int i = blockIdx.x * 256 + threadIdx.x;
    if (i < n) { __nv_bfloat16 a, b; split2(src[i], a, b); h[i] = a; l[i] = b; }
}

// ===========================================================================
// Anchor-folded terms: per batch b, anchor[b] @ {e_w1[2H:], gate_w1[2H:], router_W[2H:]}
// ===========================================================================
__global__ __launch_bounds__(256)
void anchor_pre(const float* __restrict__ anchor,
                const float* __restrict__ ew1,
                const float* __restrict__ gw1,
                const float* __restrict__ routerW,
                float* __restrict__ aux)
{
    const int b = blockIdx.y;
    const int j = blockIdx.x * 256 + threadIdx.x;
    __shared__ float as[Hd];
    for (int i = threadIdx.x; i < Hd; i += 256) as[i] = anchor[(size_t)b * Hd + i];
    __syncthreads();
    if (j >= 3*RHd + Hd + Ee) return;
    const float* wp; int stride; float* outp;
    if (j < 3*RHd) {
        int e = j >> 11, col = j & (RHd-1);
        wp = ew1 + (size_t)e*3072*RHd + (size_t)2048*RHd + col; stride = RHd;
        outp = aux + e*8*RHd + b*RHd + col;
    } else if (j < 3*RHd + Hd) {
        int col = j - 3*RHd;
        wp = gw1 + (size_t)2048*Hd + col; stride = Hd;
        outp = aux + AUX_AG1 + b*Hd + col;
    } else {
        int col = j - (3*RHd + Hd);
        wp = routerW + (size_t)2048*Ee + col; stride = Ee;
        outp = aux + AUX_ARL + b*Ee + col;
    }
    float acc = 0.f;
#pragma unroll 4
    for (int kk = 0; kk < Hd; ++kk) acc += as[kk] * wp[(size_t)kk * stride];
    *outp = acc;
}

// ===========================================================================
// LayerNorm -> combined[:,0:1024] fp32 + chi/clo
// ===========================================================================
__global__ __launch_bounds__(256)
void ln_kernel(const float* __restrict__ x,
               const float* __restrict__ gamma,
               const float* __restrict__ beta,
               float* __restrict__ combined,
               __nv_bfloat16* __restrict__ chi,
               __nv_bfloat16* __restrict__ clo)
{
    const int row = blockIdx.x;
    const int tid = threadIdx.x;
    const float* xr = x + (size_t)row * Hd;

    float v[4];
    float s = 0.f, s2 = 0.f;
#pragma unroll
    for (int i = 0; i < 4; ++i) {
        v[i] = xr[tid + i * 256];
        s += v[i]; s2 += v[i] * v[i];
    }
    __shared__ float red0[8], red1[8];
    const int lane = tid & 31, wid = tid >> 5;
#pragma unroll
    for (int o = 16; o > 0; o >>= 1) {
        s  += __shfl_xor_sync(0xffffffffu, s, o);
        s2 += __shfl_xor_sync(0xffffffffu, s2, o);
    }
    if (lane == 0) { red0[wid] = s; red1[wid] = s2; }
    __syncthreads();
    __shared__ float s_mean, s_rstd;
    if (tid == 0) {
        float ts = 0.f, ts2 = 0.f;
#pragma unroll
        for (int i = 0; i < 8; ++i) { ts += red0[i]; ts2 += red1[i]; }
        float mean = ts * (1.0f / Hd);
        float var  = ts2 * (1.0f / Hd) - mean * mean;
        s_mean = mean; s_rstd = rsqrtf(var + 1e-5f);
    }
    __syncthreads();
    const float mean = s_mean, rstd = s_rstd;

    float* crow = combined + (size_t)row * C2H;
    __nv_bfloat16* hrow = chi + (size_t)row * C2H;
    __nv_bfloat16* lrow = clo + (size_t)row * C2H;
#pragma unroll
    for (int i = 0; i < 4; ++i) {
        int c = tid + i * 256;
        float nx = (v[i] - mean) * rstd * gamma[c] + beta[c];
        crow[c] = nx;
        __nv_bfloat16 h, l; split2(nx, h, l);
        hrow[c] = h; lrow[c] = l;
    }
}

// ===========================================================================
// Cross-attention (4 tokens / block) -> combined[:,1024:2048] + chi/clo
// ===========================================================================
__global__ __launch_bounds__(256)
void attn4_kernel(const float* __restrict__ q,
                  const float* __restrict__ k,
                  const float* __restrict__ v,
                  float* __restrict__ combined,
                  __nv_bfloat16* __restrict__ chi,
                  __nv_bfloat16* __restrict__ clo)
{
    const int t0  = blockIdx.x * 4;
    const int b   = t0 >> 11;
    const int tid = threadIdx.x;
    const int lane = tid & 31, w = tid >> 5;

    __shared__ float qs[4][Hd];
    __shared__ float sc[4][Pp];

#pragma unroll
    for (int i = 0; i < 16; ++i) {
        int idx = tid + i * 256;
        qs[idx >> 10][idx & 1023] = q[(size_t)(t0 + (idx >> 10)) * Hd + (idx & 1023)];
    }
    __syncthreads();

    const float* kb = k + (size_t)b * Pp * Hd;
    for (int p = w; p < Pp; p += 8) {
        const float* kr = kb + (size_t)p * Hd;
        float d0 = 0.f, d1 = 0.f, d2 = 0.f, d3 = 0.f;
        for (int i = lane; i < Hd; i += 32) {
            float kv = kr[i];
            d0 += kv * qs[0][i]; d1 += kv * qs[1][i];
            d2 += kv * qs[2][i]; d3 += kv * qs[3][i];
        }
#pragma unroll
        for (int o = 16; o > 0; o >>= 1) {
            d0 += __shfl_xor_sync(0xffffffffu, d0, o);
            d1 += __shfl_xor_sync(0xffffffffu, d1, o);
            d2 += __shfl_xor_sync(0xffffffffu, d2, o);
            d3 += __shfl_xor_sync(0xffffffffu, d3, o);
        }
        if (lane == 0) {
            sc[0][p] = d0 * 0.03125f; sc[1][p] = d1 * 0.03125f;
            sc[2][p] = d2 * 0.03125f; sc[3][p] = d3 * 0.03125f;
        }
    }
    __syncthreads();

    if (w < 4) {
        float a = sc[w][lane], c = sc[w][lane + 32];
        float m = fmaxf(a, c);
#pragma unroll
        for (int o = 16; o > 0; o >>= 1) m = fmaxf(m, __shfl_xor_sync(0xffffffffu, m, o));
        float e1 = expf(a - m), e2 = expf(c - m);
        float ssum = e1 + e2;
#pragma unroll
        for (int o = 16; o > 0; o >>= 1) ssum += __shfl_xor_sync(0xffffffffu, ssum, o);
        float inv = 1.0f / ssum;
        sc[w][lane] = e1 * inv; sc[w][lane + 32] = e2 * inv;
    }
    __syncthreads();

    const float* vb = v + (size_t)b * Pp * Hd;
    const int c0 = tid * 4;
    float acc[4][4];
#pragma unroll
    for (int t = 0; t < 4; ++t)
#pragma unroll
        for (int j = 0; j < 4; ++j) acc[t][j] = 0.f;
    for (int p = 0; p < Pp; ++p) {
        float4 vv = *(const float4*)(vb + (size_t)p * Hd + c0);
        float w0 = sc[0][p], w1 = sc[1][p], w2 = sc[2][p], w3 = sc[3][p];
        acc[0][0] += w0 * vv.x; acc[0][1] += w0 * vv.y; acc[0][2] += w0 * vv.z; acc[0][3] += w0 * vv.w;
        acc[1][0] += w1 * vv.x; acc[1][1] += w1 * vv.y; acc[1][2] += w1 * vv.z; acc[1][3] += w1 * vv.w;
        acc[2][0] += w2 * vv.x; acc[2][1] += w2 * vv.y; acc[2][2] += w2 * vv.z; acc[2][3] += w2 * vv.w;
        acc[3][0] += w3 * vv.x; acc[3][1] += w3 * vv.y; acc[3][2] += w3 * vv.z; acc[3][3] += w3 * vv.w;
    }
#pragma unroll
    for (int t = 0; t < 4; ++t) {
        size_t base = (size_t)(t0 + t) * C2H + Hd + c0;
#pragma unroll
        for (int j = 0; j < 4; ++j) {
            float e = acc[t][j];
            combined[base + j] = e;
            __nv_bfloat16 h, l; split2(e, h, l);
            chi[base + j] = h; clo[base + j] = l;
        }
    }
}

// ===========================================================================
// Router: logits = combined[:,0:2048] @ W[0:2048,:] + b + arl[b], softmax
// ===========================================================================
__global__ __launch_bounds__(128)
void router_kernel(const float* __restrict__ combined,
                   const float* __restrict__ W,
                   const float* __restrict__ bias,
                   const float* __restrict__ aux,
                   float* __restrict__ probs)
{
    const int row = blockIdx.x;
    const int b   = row >> 11;
    const int tid = threadIdx.x;
    const int lane = tid & 31, w = tid >> 5;
    __shared__ float lg[Ee];

    if (w < Ee) {
        const float* cr = combined + (size_t)row * C2H;
        float d = 0.f;
        for (int i = lane; i < C2H; i += 32) d += cr[i] * W[(size_t)i * Ee + w];
#pragma unroll
        for (int o = 16; o > 0; o >>= 1) d += __shfl_xor_sync(0xffffffffu, d, o);
        if (lane == 0) lg[w] = d + bias[w] + aux[AUX_ARL + b*Ee + w];
    }
    __syncthreads();
    if (tid == 0) {
        float m = fmaxf(lg[0], fmaxf(lg[1], lg[2]));
        float e0 = expf(lg[0] - m), e1 = expf(lg[1] - m), e2 = expf(lg[2] - m);
        float inv = 1.0f / (e0 + e1 + e2);
        probs[(size_t)row * Ee + 0] = e0 * inv;
        probs[(size_t)row * Ee + 1] = e1 * inv;
        probs[(size_t)row * Ee + 2] = e2 * inv;
    }
}

// ===========================================================================
// mma.sync bf16x3 GEMM. CTA 128x128, 8 warps, Ktile=32, 3-stage cp.async.
// EPI 0: C = acc (fp32)
// EPI 1: v = silu(acc + bias[col] + extra[b*extN+col]); if(prob) v*=prob[row*3+pe];
//        split -> Chi/Clo (ld = ldc)
// EPI 2: v = acc + sum_e prob[row*3+e]*bias[e*Hd+col]; split -> Chi/Clo
// EPI 3: C = sigmoid(acc + bias)
// EPI 4: C = resid + gate * (acc + bias)
// ===========================================================================
#define MAT_SZ   10240
#define STG_SZ   40960
#define SMEM_DYN (3 * STG_SZ)

template<int EPI>
__global__ __launch_bounds__(256)
void mma_gemm(const __nv_bfloat16* __restrict__ Ahi, const __nv_bfloat16* __restrict__ Alo, int lda,
              const __nv_bfloat16* __restrict__ Bhi, const __nv_bfloat16* __restrict__ Blo,
              int K,
              float* __restrict__ C, int ldc,
              __nv_bfloat16* __restrict__ Chi, __nv_bfloat16* __restrict__ Clo,
              const float* __restrict__ bias,
              const float* __restrict__ extra, int extN,
              const float* __restrict__ prob, int pe,
              const float* __restrict__ gate,
              const float* __restrict__ resid)
{
    extern __shared__ char smem[];
    const uint32_t sb = smem_u32(smem);

    const int tid  = threadIdx.x;
    const int lane = tid & 31, wid = tid >> 5;
    const int bm = blockIdx.y * 128, bn = blockIdx.x * 128;
    const int m0 = (wid >> 1) * 32, n0 = (wid & 1) * 64;

    const char* gsrc[8];
    uint32_t    sdst[8];
#pragma unroll
    for (int j = 0; j < 8; ++j) {
        int c   = tid + j * 256;
        int mat = c >> 9;
        int cc  = c & 511;
        int row = cc >> 2, seg = cc & 3;
        const __nv_bfloat16* base;
        size_t stride; int r0;
        if      (mat == 0) { base = Ahi; stride = lda; r0 = bm + row; }
        else if (mat == 1) { base = Alo; stride = lda; r0 = bm + row; }
        else if (mat == 2) { base = Bhi; stride = K;   r0 = bn + row; }
        else               { base = Blo; stride = K;   r0 = bn + row; }
        gsrc[j] = (const char*)(base + (size_t)r0 * stride + seg * 8);
        sdst[j] = sb + mat * MAT_SZ + row * 80 + seg * 16;
    }

    const int NC = K >> 5;

#define ISSUE(it) do{ \
        if ((it) < NC) { \
            uint32_t so_ = ((it) % 3) * STG_SZ; \
            size_t   go_ = (size_t)(it) * 64;   \
            _Pragma("unroll") \
            for (int j = 0; j < 8; ++j) CPA(sdst[j] + so_, gsrc[j] + go_); \
        } \
        CPC(); \
    } while(0)

    ISSUE(0);
    ISSUE(1);

    float acc[2][8][4];
#pragma unroll
    for (int mi = 0; mi < 2; ++mi)
#pragma unroll
        for (int nt = 0; nt < 8; ++nt)
#pragma unroll
            for (int r = 0; r < 4; ++r) acc[mi][nt][r] = 0.f;

    const uint32_t a_off = (uint32_t)((m0 + (lane & 15)) * 80 + (lane >> 4) * 16);
    const uint32_t b_off = (uint32_t)((n0 + ((lane >> 4) & 1) * 8 + (lane & 7)) * 80
                                      + ((lane >> 3) & 1) * 16);

    for (int it = 0; it < NC; ++it) {
        const uint32_t stg = sb + (it % 3) * STG_SZ;
        CPW1();
        __syncthreads();
        ISSUE(it + 2);

#pragma unroll
        for (int ks = 0; ks < 2; ++ks) {
            uint32_t ah[2][4], al[2][4];
#pragma unroll
            for (int mi = 0; mi < 2; ++mi) {
                uint32_t ad = stg + a_off + mi * (16 * 80) + ks * 32;
                ldsm4(ah[mi], ad);
                ldsm4(al[mi], ad + MAT_SZ);
            }
            uint32_t bh[16], bl[16];
#pragma unroll
            for (int p = 0; p < 4; ++p) {
                uint32_t bd = stg + 2 * MAT_SZ + b_off + p * (16 * 80) + ks * 32;
                ldsm4(bh + p * 4, bd);
                ldsm4(bl + p * 4, bd + MAT_SZ);
            }
            // term-major: 16 independent accumulators between reuses
#pragma unroll
            for (int mi = 0; mi < 2; ++mi)
#pragma unroll
                for (int nt = 0; nt < 8; ++nt)
                    mma16816(acc[mi][nt], ah[mi], bh + nt * 2);
#pragma unroll
            for (int mi = 0; mi < 2; ++mi)
#pragma unroll
                for (int nt = 0; nt < 8; ++nt)
                    mma16816(acc[mi][nt], ah[mi], bl + nt * 2);
#pragma unroll
            for (int mi = 0; mi < 2; ++mi)
#pragma unroll
                for (int nt = 0; nt < 8; ++nt)
                    mma16816(acc[mi][nt], al[mi], bh + nt * 2);
        }
    }
    CPW0();

    // ---- epilogue ----
#pragma unroll
    for (int nt = 0; nt < 8; ++nt) {
        const int col = bn + n0 + nt * 8 + (lane & 3) * 2;
        float bia0 = 0.f, bia1 = 0.f;
        if (EPI == 1 || EPI == 3 || EPI == 4) { bia0 = bias[col]; bia1 = bias[col + 1]; }
#pragma unroll
        for (int mi = 0; mi < 2; ++mi) {
#pragma unroll
            for (int hf = 0; hf < 2; ++hf) {
                const int row = bm + m0 + mi * 16 + (lane >> 2) + hf * 8;
                float v0 = acc[mi][nt][hf * 2 + 0];
                float v1 = acc[mi][nt][hf * 2 + 1];
                const size_t off = (size_t)row * ldc + col;
                if (EPI == 0) {
                    *(float2*)(C + off) = make_float2(v0, v1);
                } else if (EPI == 1) {
                    const int b = row >> 11;
                    float e0 = extra[(size_t)b * extN + col];
                    float e1 = extra[(size_t)b * extN + col + 1];
                    float s0 = siluf(v0 + bia0 + e0), s1 = siluf(v1 + bia1 + e1);
                    if (prob) {
                        float p = prob[(size_t)row * Ee + pe];
                        s0 *= p; s1 *= p;
                    }
                    __nv_bfloat16 h0, l0, h1, l1;
                    split2(s0, h0, l0); split2(s1, h1, l1);
                    __nv_bfloat162 hv; hv.x = h0; hv.y = h1;
                    __nv_bfloat162 lv; lv.x = l0; lv.y = l1;
                    *(__nv_bfloat162*)(Chi + off) = hv;
                    *(__nv_bfloat162*)(Clo + off) = lv;
                } else if (EPI == 2) {
                    float p0 = prob[(size_t)row * Ee + 0];
                    float p1 = prob[(size_t)row * Ee + 1];
                    float p2 = prob[(size_t)row * Ee + 2];
                    float u0 = v0 + p0*bias[col]   + p1*bias[Hd+col]   + p2*bias[2*Hd+col];
                    float u1 = v1 + p0*bias[col+1] + p1*bias[Hd+col+1] + p2*bias[2*Hd+col+1];
                    __nv_bfloat16 h0, l0, h1, l1;
                    split2(u0, h0, l0); split2(u1, h1, l1);
                    __nv_bfloat162 hv; hv.x = h0; hv.y = h1;
                    __nv_bfloat162 lv; lv.x = l0; lv.y = l1;
                    *(__nv_bfloat162*)(Chi + off) = hv;
                    *(__nv_bfloat162*)(Clo + off) = lv;
                } else if (EPI == 3) {
                    *(float2*)(C + off) = make_float2(sigmf(v0 + bia0), sigmf(v1 + bia1));
                } else {
                    float2 gg = *(const float2*)(gate + off);
                    float2 xx = *(const float2*)(resid + off);
                    *(float2*)(C + off) =
                        make_float2(xx.x + gg.x * (v0 + bia0), xx.y + gg.y * (v1 + bia1));
                }
            }
        }
    }
#undef ISSUE
}

// ===========================================================================
// Launch
// ===========================================================================
extern "C" void kernel_launch(void* const* d_in, const int* in_sizes, int n_in,
                              void* d_out, int out_size)
{
    const float* x       = (const float*)d_in[0];
    const float* anchor  = (const float*)d_in[1];
    const float* proto   = (const float*)d_in[2];
    const float* gamma   = (const float*)d_in[3];
    const float* beta    = (const float*)d_in[4];
    const float* Wq      = (const float*)d_in[5];
    const float* Wk      = (const float*)d_in[6];
    const float* Wv      = (const float*)d_in[7];
    const float* routerW = (const float*)d_in[8];
    const float* routerB = (const float*)d_in[9];
    const float* ew1     = (const float*)d_in[10];
    const float* eb1     = (const float*)d_in[11];
    const float* ew2     = (const float*)d_in[12];
    const float* eb2     = (const float*)d_in[13];
    const float* gw1     = (const float*)d_in[14];
    const float* gb1     = (const float*)d_in[15];
    const float* gw2     = (const float*)d_in[16];
    const float* gb2     = (const float*)d_in[17];
    const float* outw    = (const float*)d_in[18];
    const float* outb    = (const float*)d_in[19];
    float* out = (float*)d_out;

    float *combined, *q, *k, *v, *gate, *probs, *aux;
    __nv_bfloat16 *chi, *clo, *hhi, *hlo, *g1hi, *g1lo, *rhi, *rlo, *phi, *plo, *wth, *wtl;
    cudaGetSymbolAddress((void**)&combined, g_combined);
    cudaGetSymbolAddress((void**)&chi, g_chi);
    cudaGetSymbolAddress((void**)&clo, g_clo);
    cudaGetSymbolAddress((void**)&hhi, g_hhi);
    cudaGetSymbolAddress((void**)&hlo, g_hlo);
    cudaGetSymbolAddress((void**)&g1hi, g_g1hi);
    cudaGetSymbolAddress((void**)&g1lo, g_g1lo);
    cudaGetSymbolAddress((void**)&rhi, g_rhi);
    cudaGetSymbolAddress((void**)&rlo, g_rlo);
    cudaGetSymbolAddress((void**)&phi, g_phi);
    cudaGetSymbolAddress((void**)&plo, g_plo);
    cudaGetSymbolAddress((void**)&q, g_q);
    cudaGetSymbolAddress((void**)&k, g_k);
    cudaGetSymbolAddress((void**)&v, g_v);
    cudaGetSymbolAddress((void**)&gate, g_gate);
    cudaGetSymbolAddress((void**)&probs, g_probs);
    cudaGetSymbolAddress((void**)&aux, g_aux);
    cudaGetSymbolAddress((void**)&wth, g_wT_hi);
    cudaGetSymbolAddress((void**)&wtl, g_wT_lo);

    cudaFuncSetAttribute(mma_gemm<0>, cudaFuncAttributeMaxDynamicSharedMemorySize, SMEM_DYN);
    cudaFuncSetAttribute(mma_gemm<1>, cudaFuncAttributeMaxDynamicSharedMemorySize, SMEM_DYN);
    cudaFuncSetAttribute(mma_gemm<2>, cudaFuncAttributeMaxDynamicSharedMemorySize, SMEM_DYN);
    cudaFuncSetAttribute(mma_gemm<3>, cudaFuncAttributeMaxDynamicSharedMemorySize, SMEM_DYN);
    cudaFuncSetAttribute(mma_gemm<4>, cudaFuncAttributeMaxDynamicSharedMemorySize, SMEM_DYN);

    // ---- weight prep ----
    trans_split<<<dim3(Hd/32,  Hd/32),  256>>>(Wq,   Hd,  wth + WQ_OFF,  wtl + WQ_OFF,  Hd,  0);
    trans_split<<<dim3(Hd/32,  Hd/32),  256>>>(Wk,   Hd,  wth + WK_OFF,  wtl + WK_OFF,  Hd,  0);
    trans_split<<<dim3(Hd/32,  Hd/32),  256>>>(Wv,   Hd,  wth + WV_OFF,  wtl + WV_OFF,  Hd,  0);
    trans_split<<<dim3(Hd/32,  C2H/32), 256>>>(gw1,  Hd,  wth + GW1_OFF, wtl + GW1_OFF, C2H, 0);
    trans_split<<<dim3(Hd/32,  Hd/32),  256>>>(gw2,  Hd,  wth + GW2_OFF, wtl + GW2_OFF, Hd,  0);
    trans_split<<<dim3(Hd/32,  Hd/32),  256>>>(outw, Hd,  wth + OW_OFF,  wtl + OW_OFF,  Hd,  0);
    for (int e = 0; e < Ee; ++e) {
        trans_split<<<dim3(RHd/32, C2H/32), 256>>>(ew1 + (size_t)e*3072*RHd, RHd,
            wth + EW1_OFF + (size_t)e*RHd*C2H, wtl + EW1_OFF + (size_t)e*RHd*C2H, C2H, 0);
        trans_split<<<dim3(Hd/32, RHd/32), 256>>>(ew2 + (size_t)e*RHd*Hd, Hd,
            wth + EW2_OFF, wtl + EW2_OFF, CK6, e*RHd);
    }
    split_arr<<<(Bb*Pp*Hd + 255)/256, 256>>>(proto, phi, plo, Bb*Pp*Hd);

    // ---- anchor folding ----
    anchor_pre<<<dim3(29, Bb), 256>>>(anchor, ew1, gw1, routerW, aux);

    // ---- LN ----
    ln_kernel<<<BT, 256>>>(x, gamma, beta, combined, chi, clo);

    // ---- q, k, v ----
    mma_gemm<0><<<dim3(Hd/128, BT/128), 256, SMEM_DYN>>>(
        chi, clo, C2H, wth + WQ_OFF, wtl + WQ_OFF, Hd,
        q, Hd, nullptr, nullptr, nullptr, nullptr, 0, nullptr, 0, nullptr, nullptr);
    mma_gemm<0><<<dim3(Hd/128, (Bb*Pp)/128), 256, SMEM_DYN>>>(
        phi, plo, Hd, wth + WK_OFF, wtl + WK_OFF, Hd,
        k, Hd, nullptr, nullptr, nullptr, nullptr, 0, nullptr, 0, nullptr, nullptr);
    mma_gemm<0><<<dim3(Hd/128, (Bb*Pp)/128), 256, SMEM_DYN>>>(
        phi, plo, Hd, wth + WV_OFF, wtl + WV_OFF, Hd,
        v, Hd, nullptr, nullptr, nullptr, nullptr, 0, nullptr, 0, nullptr, nullptr);

    // ---- attention ----
    attn4_kernel<<<BT/4, 256>>>(q, k, v, combined, chi, clo);

    // ---- router ----
    router_kernel<<<BT, 128>>>(combined, routerW, routerB, aux, probs);

    // ---- expert up (prob folded) -> h'[BT,6144] ----
    for (int e = 0; e < Ee; ++e) {
        mma_gemm<1><<<dim3(RHd/128, BT/128), 256, SMEM_DYN>>>(
            chi, clo, C2H,
            wth + EW1_OFF + (size_t)e*RHd*C2H, wtl + EW1_OFF + (size_t)e*RHd*C2H, C2H,
            nullptr, CK6, hhi + (size_t)e*RHd, hlo + (size_t)e*RHd,
            eb1 + (size_t)e*RHd, aux + e*8*RHd, RHd, probs, e, nullptr, nullptr);
    }

    // ---- fused expert down: routed = h' @ W2cat + sum_e p_e b2_e -> rhi/rlo ----
    mma_gemm<2><<<dim3(Hd/128, BT/128), 256, SMEM_DYN>>>(
        hhi, hlo, CK6, wth + EW2_OFF, wtl + EW2_OFF, CK6,
        nullptr, Hd, rhi, rlo, eb2, nullptr, 0, probs, 0, nullptr, nullptr);

    // ---- gate MLP ----
    mma_gemm<1><<<dim3(Hd/128, BT/128), 256, SMEM_DYN>>>(
        chi, clo, C2H, wth + GW1_OFF, wtl + GW1_OFF, C2H,
        nullptr, Hd, g1hi, g1lo, gb1, aux + AUX_AG1, Hd, nullptr, 0, nullptr, nullptr);
    mma_gemm<3><<<dim3(Hd/128, BT/128), 256, SMEM_DYN>>>(
        g1hi, g1lo, Hd, wth + GW2_OFF, wtl + GW2_OFF, Hd,
        gate, Hd, nullptr, nullptr, gb2, nullptr, 0, nullptr, 0, nullptr, nullptr);

    // ---- final ----
    mma_gemm<4><<<dim3(Hd/128, BT/128), 256, SMEM_DYN>>>(
        rhi, rlo, Hd, wth + OW_OFF, wtl + OW_OFF, Hd,
        out, Hd, nullptr, nullptr, outb, nullptr, 0, nullptr, 0, gate, x);
}

// round 5
// speedup vs baseline: 2.9240x; 1.0478x over previous
#include <cuda_runtime.h>
#include <cuda_bf16.h>
#include <math.h>
#include <stdint.h>

#define Hd   1024
#define Bb   8
#define Pp   64
#define Ee   3
#define RHd  2048
#define BT   16384
#define C2H  2048
#define CK6  6144

// ===========================================================================
// PTX helpers — baseline (sm_80-class) instructions only.
// ===========================================================================
__device__ __forceinline__ uint32_t smem_u32(const void* p){
    uint32_t a;
    asm("{ .reg .u64 t; cvta.to.shared.u64 t, %1; cvt.u32.u64 %0, t; }" : "=r"(a) : "l"(p));
    return a;
}
#define CPA(dst, src) asm volatile("cp.async.cg.shared.global [%0], [%1], 16;" :: "r"(dst), "l"(src))
#define CPC()  asm volatile("cp.async.commit_group;" ::: "memory")
#define CPW1() asm volatile("cp.async.wait_group 1;" ::: "memory")
#define CPW0() asm volatile("cp.async.wait_group 0;" ::: "memory")

__device__ __forceinline__ void ldsm4(uint32_t* r, uint32_t addr){
    asm volatile("ldmatrix.sync.aligned.m8n8.x4.shared.b16 {%0,%1,%2,%3}, [%4];"
        : "=r"(r[0]), "=r"(r[1]), "=r"(r[2]), "=r"(r[3]) : "r"(addr));
}
__device__ __forceinline__ void mma16816(float* d, const uint32_t* a, const uint32_t* b){
    asm("mma.sync.aligned.m16n8k16.row.col.f32.bf16.bf16.f32 "
        "{%0,%1,%2,%3}, {%4,%5,%6,%7}, {%8,%9}, {%0,%1,%2,%3};"
        : "+f"(d[0]), "+f"(d[1]), "+f"(d[2]), "+f"(d[3])
        : "r"(a[0]), "r"(a[1]), "r"(a[2]), "r"(a[3]), "r"(b[0]), "r"(b[1]));
}

__device__ __forceinline__ void split2(float v, __nv_bfloat16& h, __nv_bfloat16& l){
    h = __float2bfloat16(v);
    l = __float2bfloat16(v - __bfloat162float(h));
}
__device__ __forceinline__ float siluf(float x){ return x / (1.0f + expf(-x)); }
__device__ __forceinline__ float sigmf(float x){ return 1.0f / (1.0f + expf(-x)); }

// ===========================================================================
// Scratch
// ===========================================================================
__device__ float g_combined[(size_t)BT * C2H];
__device__ __nv_bfloat16 g_chi[(size_t)BT * C2H];
__device__ __nv_bfloat16 g_clo[(size_t)BT * C2H];
__device__ __nv_bfloat16 g_hhi[(size_t)BT * CK6];
__device__ __nv_bfloat16 g_hlo[(size_t)BT * CK6];
__device__ __nv_bfloat16 g_g1hi[(size_t)BT * Hd];
__device__ __nv_bfloat16 g_g1lo[(size_t)BT * Hd];
__device__ __nv_bfloat16 g_rhi[(size_t)BT * Hd];
__device__ __nv_bfloat16 g_rlo[(size_t)BT * Hd];
__device__ __nv_bfloat16 g_phi[(size_t)Bb * Pp * Hd];
__device__ __nv_bfloat16 g_plo[(size_t)Bb * Pp * Hd];
__device__ float g_q[(size_t)BT * Hd];
__device__ float g_k[(size_t)Bb * Pp * Hd];
__device__ float g_v[(size_t)Bb * Pp * Hd];
__device__ float g_gate[(size_t)BT * Hd];
__device__ float g_probs[(size_t)BT * Ee];
__device__ float g_aux[3*8*2048 + 8*1024 + 8*3];
#define AUX_AG1 49152
#define AUX_ARL 57344

#define WQ_OFF   ((size_t)0)
#define WK_OFF   (WQ_OFF  + (size_t)Hd*Hd)
#define WV_OFF   (WK_OFF  + (size_t)Hd*Hd)
#define GW1_OFF  (WV_OFF  + (size_t)Hd*Hd)
#define GW2_OFF  (GW1_OFF + (size_t)Hd*C2H)
#define OW_OFF   (GW2_OFF + (size_t)Hd*Hd)
#define EW1_OFF  (OW_OFF  + (size_t)Hd*Hd)
#define EW2_OFF  (EW1_OFF + (size_t)Ee*RHd*C2H)
#define WT_TOTAL (EW2_OFF + (size_t)Hd*CK6)
__device__ __nv_bfloat16 g_wT_hi[WT_TOTAL];
__device__ __nv_bfloat16 g_wT_lo[WT_TOTAL];

// ===========================================================================
// Weight transpose + split
// ===========================================================================
__global__ __launch_bounds__(256)
void trans_split(const float* __restrict__ W, int N,
                 __nv_bfloat16* __restrict__ Th, __nv_bfloat16* __restrict__ Tl,
                 int ldT, int koff)
{
    __shared__ float t[32][33];
    const int n0 = blockIdx.x * 32, k0 = blockIdx.y * 32;
    const int tx = threadIdx.x & 31, ty = threadIdx.x >> 5;
#pragma unroll
    for (int i = 0; i < 4; ++i)
        t[ty + i * 8][tx] = W[(size_t)(k0 + ty + i * 8) * N + n0 + tx];
    __syncthreads();
#pragma unroll
    for (int i = 0; i < 4; ++i) {
        float v = t[tx][ty + i * 8];
        size_t o = (size_t)(n0 + ty + i * 8) * ldT + koff + k0 + tx;
        __nv_bfloat16 h, l; split2(v, h, l);
        Th[o] = h; Tl[o] = l;
    }
}

__global__ __launch_bounds__(256)
void split_arr(const float* __restrict__ src, __nv_bfloat16* __restrict__ h,
               __nv_bfloat16* __restrict__ l, int n)
{
    int i = blockIdx.x * 256 + threadIdx.x;
    if (i < n) { __nv_bfloat16 a, b; split2(src[i], a, b); h[i] = a; l[i] = b; }
}

// ===========================================================================
// Anchor-folded terms
// ===========================================================================
__global__ __launch_bounds__(256)
void anchor_pre(const float* __restrict__ anchor,
                const float* __restrict__ ew1,
                const float* __restrict__ gw1,
                const float* __restrict__ routerW,
                float* __restrict__ aux)
{
    const int b = blockIdx.y;
    const int j = blockIdx.x * 256 + threadIdx.x;
    __shared__ float as[Hd];
    for (int i = threadIdx.x; i < Hd; i += 256) as[i] = anchor[(size_t)b * Hd + i];
    __syncthreads();
    if (j >= 3*RHd + Hd + Ee) return;
    const float* wp; int stride; float* outp;
    if (j < 3*RHd) {
        int e = j >> 11, col = j & (RHd-1);
        wp = ew1 + (size_t)e*3072*RHd + (size_t)2048*RHd + col; stride = RHd;
        outp = aux + e*8*RHd + b*RHd + col;
    } else if (j < 3*RHd + Hd) {
        int col = j - 3*RHd;
        wp = gw1 + (size_t)2048*Hd + col; stride = Hd;
        outp = aux + AUX_AG1 + b*Hd + col;
    } else {
        int col = j - (3*RHd + Hd);
        wp = routerW + (size_t)2048*Ee + col; stride = Ee;
        outp = aux + AUX_ARL + b*Ee + col;
    }
    float acc = 0.f;
#pragma unroll 4
    for (int kk = 0; kk < Hd; ++kk) acc += as[kk] * wp[(size_t)kk * stride];
    *outp = acc;
}

// ===========================================================================
// LayerNorm
// ===========================================================================
__global__ __launch_bounds__(256)
void ln_kernel(const float* __restrict__ x,
               const float* __restrict__ gamma,
               const float* __restrict__ beta,
               float* __restrict__ combined,
               __nv_bfloat16* __restrict__ chi,
               __nv_bfloat16* __restrict__ clo)
{
    const int row = blockIdx.x;
    const int tid = threadIdx.x;
    const float* xr = x + (size_t)row * Hd;

    float v[4];
    float s = 0.f, s2 = 0.f;
#pragma unroll
    for (int i = 0; i < 4; ++i) {
        v[i] = xr[tid + i * 256];
        s += v[i]; s2 += v[i] * v[i];
    }
    __shared__ float red0[8], red1[8];
    const int lane = tid & 31, wid = tid >> 5;
#pragma unroll
    for (int o = 16; o > 0; o >>= 1) {
        s  += __shfl_xor_sync(0xffffffffu, s, o);
        s2 += __shfl_xor_sync(0xffffffffu, s2, o);
    }
    if (lane == 0) { red0[wid] = s; red1[wid] = s2; }
    __syncthreads();
    __shared__ float s_mean, s_rstd;
    if (tid == 0) {
        float ts = 0.f, ts2 = 0.f;
#pragma unroll
        for (int i = 0; i < 8; ++i) { ts += red0[i]; ts2 += red1[i]; }
        float mean = ts * (1.0f / Hd);
        float var  = ts2 * (1.0f / Hd) - mean * mean;
        s_mean = mean; s_rstd = rsqrtf(var + 1e-5f);
    }
    __syncthreads();
    const float mean = s_mean, rstd = s_rstd;

    float* crow = combined + (size_t)row * C2H;
    __nv_bfloat16* hrow = chi + (size_t)row * C2H;
    __nv_bfloat16* lrow = clo + (size_t)row * C2H;
#pragma unroll
    for (int i = 0; i < 4; ++i) {
        int c = tid + i * 256;
        float nx = (v[i] - mean) * rstd * gamma[c] + beta[c];
        crow[c] = nx;
        __nv_bfloat16 h, l; split2(nx, h, l);
        hrow[c] = h; lrow[c] = l;
    }
}

// ===========================================================================
// Cross-attention (4 tokens / block)
// ===========================================================================
__global__ __launch_bounds__(256)
void attn4_kernel(const float* __restrict__ q,
                  const float* __restrict__ k,
                  const float* __restrict__ v,
                  float* __restrict__ combined,
                  __nv_bfloat16* __restrict__ chi,
                  __nv_bfloat16* __restrict__ clo)
{
    const int t0  = blockIdx.x * 4;
    const int b   = t0 >> 11;
    const int tid = threadIdx.x;
    const int lane = tid & 31, w = tid >> 5;

    __shared__ float qs[4][Hd];
    __shared__ float sc[4][Pp];

#pragma unroll
    for (int i = 0; i < 16; ++i) {
        int idx = tid + i * 256;
        qs[idx >> 10][idx & 1023] = q[(size_t)(t0 + (idx >> 10)) * Hd + (idx & 1023)];
    }
    __syncthreads();

    const float* kb = k + (size_t)b * Pp * Hd;
    for (int p = w; p < Pp; p += 8) {
        const float* kr = kb + (size_t)p * Hd;
        float d0 = 0.f, d1 = 0.f, d2 = 0.f, d3 = 0.f;
        for (int i = lane; i < Hd; i += 32) {
            float kv = kr[i];
            d0 += kv * qs[0][i]; d1 += kv * qs[1][i];
            d2 += kv * qs[2][i]; d3 += kv * qs[3][i];
        }
#pragma unroll
        for (int o = 16; o > 0; o >>= 1) {
            d0 += __shfl_xor_sync(0xffffffffu, d0, o);
            d1 += __shfl_xor_sync(0xffffffffu, d1, o);
            d2 += __shfl_xor_sync(0xffffffffu, d2, o);
            d3 += __shfl_xor_sync(0xffffffffu, d3, o);
        }
        if (lane == 0) {
            sc[0][p] = d0 * 0.03125f; sc[1][p] = d1 * 0.03125f;
            sc[2][p] = d2 * 0.03125f; sc[3][p] = d3 * 0.03125f;
        }
    }
    __syncthreads();

    if (w < 4) {
        float a = sc[w][lane], c = sc[w][lane + 32];
        float m = fmaxf(a, c);
#pragma unroll
        for (int o = 16; o > 0; o >>= 1) m = fmaxf(m, __shfl_xor_sync(0xffffffffu, m, o));
        float e1 = expf(a - m), e2 = expf(c - m);
        float ssum = e1 + e2;
#pragma unroll
        for (int o = 16; o > 0; o >>= 1) ssum += __shfl_xor_sync(0xffffffffu, ssum, o);
        float inv = 1.0f / ssum;
        sc[w][lane] = e1 * inv; sc[w][lane + 32] = e2 * inv;
    }
    __syncthreads();

    const float* vb = v + (size_t)b * Pp * Hd;
    const int c0 = tid * 4;
    float acc[4][4];
#pragma unroll
    for (int t = 0; t < 4; ++t)
#pragma unroll
        for (int j = 0; j < 4; ++j) acc[t][j] = 0.f;
    for (int p = 0; p < Pp; ++p) {
        float4 vv = *(const float4*)(vb + (size_t)p * Hd + c0);
        float w0 = sc[0][p], w1 = sc[1][p], w2 = sc[2][p], w3 = sc[3][p];
        acc[0][0] += w0 * vv.x; acc[0][1] += w0 * vv.y; acc[0][2] += w0 * vv.z; acc[0][3] += w0 * vv.w;
        acc[1][0] += w1 * vv.x; acc[1][1] += w1 * vv.y; acc[1][2] += w1 * vv.z; acc[1][3] += w1 * vv.w;
        acc[2][0] += w2 * vv.x; acc[2][1] += w2 * vv.y; acc[2][2] += w2 * vv.z; acc[2][3] += w2 * vv.w;
        acc[3][0] += w3 * vv.x; acc[3][1] += w3 * vv.y; acc[3][2] += w3 * vv.z; acc[3][3] += w3 * vv.w;
    }
#pragma unroll
    for (int t = 0; t < 4; ++t) {
        size_t base = (size_t)(t0 + t) * C2H + Hd + c0;
#pragma unroll
        for (int j = 0; j < 4; ++j) {
            float e = acc[t][j];
            combined[base + j] = e;
            __nv_bfloat16 h, l; split2(e, h, l);
            chi[base + j] = h; clo[base + j] = l;
        }
    }
}

// ===========================================================================
// Router
// ===========================================================================
__global__ __launch_bounds__(128)
void router_kernel(const float* __restrict__ combined,
                   const float* __restrict__ W,
                   const float* __restrict__ bias,
                   const float* __restrict__ aux,
                   float* __restrict__ probs)
{
    const int row = blockIdx.x;
    const int b   = row >> 11;
    const int tid = threadIdx.x;
    const int lane = tid & 31, w = tid >> 5;
    __shared__ float lg[Ee];

    if (w < Ee) {
        const float* cr = combined + (size_t)row * C2H;
        float d = 0.f;
        for (int i = lane; i < C2H; i += 32) d += cr[i] * W[(size_t)i * Ee + w];
#pragma unroll
        for (int o = 16; o > 0; o >>= 1) d += __shfl_xor_sync(0xffffffffu, d, o);
        if (lane == 0) lg[w] = d + bias[w] + aux[AUX_ARL + b*Ee + w];
    }
    __syncthreads();
    if (tid == 0) {
        float m = fmaxf(lg[0], fmaxf(lg[1], lg[2]));
        float e0 = expf(lg[0] - m), e1 = expf(lg[1] - m), e2 = expf(lg[2] - m);
        float inv = 1.0f / (e0 + e1 + e2);
        probs[(size_t)row * Ee + 0] = e0 * inv;
        probs[(size_t)row * Ee + 1] = e1 * inv;
        probs[(size_t)row * Ee + 2] = e2 * inv;
    }
}

// ===========================================================================
// mma.sync bf16x3 GEMM. CTA 256x128, 16 warps (8m x 2n), Ktile=32,
// 3-stage cp.async. Per-iter: 48KB load, 6.3 MFLOP -> below LTS cap.
// EPI 0: C = acc
// EPI 1: v = silu(acc + bias + extra[b]); (*prob) -> Chi/Clo
// EPI 2: v = acc + sum_e p_e b2_e -> Chi/Clo
// EPI 3: C = sigmoid(acc + bias)
// EPI 4: C = resid + gate * (acc + bias)
// ===========================================================================
#define A_MAT_SZ 20480            // 256 * 80
#define B_MAT_SZ 10240            // 128 * 80
#define STG_SZ   61440            // 2*A + 2*B
#define SMEM_DYN (3 * STG_SZ)     // 184320

template<int EPI>
__global__ __launch_bounds__(512)
void mma_gemm(const __nv_bfloat16* __restrict__ Ahi, const __nv_bfloat16* __restrict__ Alo, int lda,
              const __nv_bfloat16* __restrict__ Bhi, const __nv_bfloat16* __restrict__ Blo,
              int K,
              float* __restrict__ C, int ldc,
              __nv_bfloat16* __restrict__ Chi, __nv_bfloat16* __restrict__ Clo,
              const float* __restrict__ bias,
              const float* __restrict__ extra, int extN,
              const float* __restrict__ prob, int pe,
              const float* __restrict__ gate,
              const float* __restrict__ resid)
{
    extern __shared__ char smem[];
    const uint32_t sb = smem_u32(smem);

    const int tid  = threadIdx.x;
    const int lane = tid & 31, wid = tid >> 5;      // 16 warps
    const int bm = blockIdx.y * 256, bn = blockIdx.x * 128;
    const int m0 = (wid >> 1) * 32, n0 = (wid & 1) * 64;

    // 3072 16B chunks / iter, 6 per thread.
    // chunks: [0,1024) Ahi, [1024,2048) Alo, [2048,2560) Bhi, [2560,3072) Blo
    const char* gsrc[6];
    uint32_t    sdst[6];
#pragma unroll
    for (int j = 0; j < 6; ++j) {
        int c = tid + j * 512;
        const __nv_bfloat16* base;
        size_t stride; int r0, row, seg; uint32_t soff;
        if (c < 2048) {
            int cc = c & 1023;
            row = cc >> 2; seg = cc & 3;
            base = (c < 1024) ? Ahi : Alo; stride = lda; r0 = bm + row;
            soff = ((c < 1024) ? 0u : A_MAT_SZ) + row * 80 + seg * 16;
        } else {
            int cc = c & 511;
            row = cc >> 2; seg = cc & 3;
            base = (c < 2560) ? Bhi : Blo; stride = K; r0 = bn + row;
            soff = 2*A_MAT_SZ + ((c < 2560) ? 0u : B_MAT_SZ) + row * 80 + seg * 16;
        }
        gsrc[j] = (const char*)(base + (size_t)r0 * stride + seg * 8);
        sdst[j] = sb + soff;
    }

    const int NC = K >> 5;

#define ISSUE(it) do{ \
        if ((it) < NC) { \
            uint32_t so_ = ((it) % 3) * STG_SZ; \
            size_t   go_ = (size_t)(it) * 64;   \
            _Pragma("unroll") \
            for (int j = 0; j < 6; ++j) CPA(sdst[j] + so_, gsrc[j] + go_); \
        } \
        CPC(); \
    } while(0)

    ISSUE(0);
    ISSUE(1);

    float acc[2][8][4];
#pragma unroll
    for (int mi = 0; mi < 2; ++mi)
#pragma unroll
        for (int nt = 0; nt < 8; ++nt)
#pragma unroll
            for (int r = 0; r < 4; ++r) acc[mi][nt][r] = 0.f;

    const uint32_t a_off = (uint32_t)((m0 + (lane & 15)) * 80 + (lane >> 4) * 16);
    const uint32_t b_off = (uint32_t)(2*A_MAT_SZ + (n0 + ((lane >> 4) & 1) * 8 + (lane & 7)) * 80
                                      + ((lane >> 3) & 1) * 16);

    for (int it = 0; it < NC; ++it) {
        const uint32_t stg = sb + (it % 3) * STG_SZ;
        CPW1();
        __syncthreads();
        ISSUE(it + 2);

#pragma unroll
        for (int ks = 0; ks < 2; ++ks) {
            uint32_t ah[2][4], al[2][4];
#pragma unroll
            for (int mi = 0; mi < 2; ++mi) {
                uint32_t ad = stg + a_off + mi * (16 * 80) + ks * 32;
                ldsm4(ah[mi], ad);
                ldsm4(al[mi], ad + A_MAT_SZ);
            }
            // B in two nt-halves to cap register pressure
#pragma unroll
            for (int h = 0; h < 2; ++h) {
                uint32_t bh[8], bl[8];
#pragma unroll
                for (int p = 0; p < 2; ++p) {
                    uint32_t bd = stg + b_off + (h * 2 + p) * (16 * 80) + ks * 32;
                    ldsm4(bh + p * 4, bd);
                    ldsm4(bl + p * 4, bd + B_MAT_SZ);
                }
                // term-major: 8 independent accumulators between reuses
#pragma unroll
                for (int mi = 0; mi < 2; ++mi)
#pragma unroll
                    for (int nq = 0; nq < 4; ++nq)
                        mma16816(acc[mi][h * 4 + nq], ah[mi], bh + nq * 2);
#pragma unroll
                for (int mi = 0; mi < 2; ++mi)
#pragma unroll
                    for (int nq = 0; nq < 4; ++nq)
                        mma16816(acc[mi][h * 4 + nq], ah[mi], bl + nq * 2);
#pragma unroll
                for (int mi = 0; mi < 2; ++mi)
#pragma unroll
                    for (int nq = 0; nq < 4; ++nq)
                        mma16816(acc[mi][h * 4 + nq], al[mi], bh + nq * 2);
            }
        }
    }
    CPW0();

    // ---- epilogue ----
#pragma unroll
    for (int nt = 0; nt < 8; ++nt) {
        const int col = bn + n0 + nt * 8 + (lane & 3) * 2;
        float bia0 = 0.f, bia1 = 0.f;
        if (EPI == 1 || EPI == 3 || EPI == 4) { bia0 = bias[col]; bia1 = bias[col + 1]; }
#pragma unroll
        for (int mi = 0; mi < 2; ++mi) {
#pragma unroll
            for (int hf = 0; hf < 2; ++hf) {
                const int row = bm + m0 + mi * 16 + (lane >> 2) + hf * 8;
                float v0 = acc[mi][nt][hf * 2 + 0];
                float v1 = acc[mi][nt][hf * 2 + 1];
                const size_t off = (size_t)row * ldc + col;
                if (EPI == 0) {
                    *(float2*)(C + off) = make_float2(v0, v1);
                } else if (EPI == 1) {
                    const int b = row >> 11;
                    float e0 = extra[(size_t)b * extN + col];
                    float e1 = extra[(size_t)b * extN + col + 1];
                    float s0 = siluf(v0 + bia0 + e0), s1 = siluf(v1 + bia1 + e1);
                    if (prob) {
                        float p = prob[(size_t)row * Ee + pe];
                        s0 *= p; s1 *= p;
                    }
                    __nv_bfloat16 h0, l0, h1, l1;
                    split2(s0, h0, l0); split2(s1, h1, l1);
                    __nv_bfloat162 hv; hv.x = h0; hv.y = h1;
                    __nv_bfloat162 lv; lv.x = l0; lv.y = l1;
                    *(__nv_bfloat162*)(Chi + off) = hv;
                    *(__nv_bfloat162*)(Clo + off) = lv;
                } else if (EPI == 2) {
                    float p0 = prob[(size_t)row * Ee + 0];
                    float p1 = prob[(size_t)row * Ee + 1];
                    float p2 = prob[(size_t)row * Ee + 2];
                    float u0 = v0 + p0*bias[col]   + p1*bias[Hd+col]   + p2*bias[2*Hd+col];
                    float u1 = v1 + p0*bias[col+1] + p1*bias[Hd+col+1] + p2*bias[2*Hd+col+1];
                    __nv_bfloat16 h0, l0, h1, l1;
                    split2(u0, h0, l0); split2(u1, h1, l1);
                    __nv_bfloat162 hv; hv.x = h0; hv.y = h1;
                    __nv_bfloat162 lv; lv.x = l0; lv.y = l1;
                    *(__nv_bfloat162*)(Chi + off) = hv;
                    *(__nv_bfloat162*)(Clo + off) = lv;
                } else if (EPI == 3) {
                    *(float2*)(C + off) = make_float2(sigmf(v0 + bia0), sigmf(v1 + bia1));
                } else {
                    float2 gg = *(const float2*)(gate + off);
                    float2 xx = *(const float2*)(resid + off);
                    *(float2*)(C + off) =
                        make_float2(xx.x + gg.x * (v0 + bia0), xx.y + gg.y * (v1 + bia1));
                }
            }
        }
    }
#undef ISSUE
}

// ===========================================================================
// Launch
// ===========================================================================
extern "C" void kernel_launch(void* const* d_in, const int* in_sizes, int n_in,
                              void* d_out, int out_size)
{
    const float* x       = (const float*)d_in[0];
    const float* anchor  = (const float*)d_in[1];
    const float* proto   = (const float*)d_in[2];
    const float* gamma   = (const float*)d_in[3];
    const float* beta    = (const float*)d_in[4];
    const float* Wq      = (const float*)d_in[5];
    const float* Wk      = (const float*)d_in[6];
    const float* Wv      = (const float*)d_in[7];
    const float* routerW = (const float*)d_in[8];
    const float* routerB = (const float*)d_in[9];
    const float* ew1     = (const float*)d_in[10];
    const float* eb1     = (const float*)d_in[11];
    const float* ew2     = (const float*)d_in[12];
    const float* eb2     = (const float*)d_in[13];
    const float* gw1     = (const float*)d_in[14];
    const float* gb1     = (const float*)d_in[15];
    const float* gw2     = (const float*)d_in[16];
    const float* gb2     = (const float*)d_in[17];
    const float* outw    = (const float*)d_in[18];
    const float* outb    = (const float*)d_in[19];
    float* out = (float*)d_out;

    float *combined, *q, *k, *v, *gate, *probs, *aux;
    __nv_bfloat16 *chi, *clo, *hhi, *hlo, *g1hi, *g1lo, *rhi, *rlo, *phi, *plo, *wth, *wtl;
    cudaGetSymbolAddress((void**)&combined, g_combined);
    cudaGetSymbolAddress((void**)&chi, g_chi);
    cudaGetSymbolAddress((void**)&clo, g_clo);
    cudaGetSymbolAddress((void**)&hhi, g_hhi);
    cudaGetSymbolAddress((void**)&hlo, g_hlo);
    cudaGetSymbolAddress((void**)&g1hi, g_g1hi);
    cudaGetSymbolAddress((void**)&g1lo, g_g1lo);
    cudaGetSymbolAddress((void**)&rhi, g_rhi);
    cudaGetSymbolAddress((void**)&rlo, g_rlo);
    cudaGetSymbolAddress((void**)&phi, g_phi);
    cudaGetSymbolAddress((void**)&plo, g_plo);
    cudaGetSymbolAddress((void**)&q, g_q);
    cudaGetSymbolAddress((void**)&k, g_k);
    cudaGetSymbolAddress((void**)&v, g_v);
    cudaGetSymbolAddress((void**)&gate, g_gate);
    cudaGetSymbolAddress((void**)&probs, g_probs);
    cudaGetSymbolAddress((void**)&aux, g_aux);
    cudaGetSymbolAddress((void**)&wth, g_wT_hi);
    cudaGetSymbolAddress((void**)&wtl, g_wT_lo);

    cudaFuncSetAttribute(mma_gemm<0>, cudaFuncAttributeMaxDynamicSharedMemorySize, SMEM_DYN);
    cudaFuncSetAttribute(mma_gemm<1>, cudaFuncAttributeMaxDynamicSharedMemorySize, SMEM_DYN);
    cudaFuncSetAttribute(mma_gemm<2>, cudaFuncAttributeMaxDynamicSharedMemorySize, SMEM_DYN);
    cudaFuncSetAttribute(mma_gemm<3>, cudaFuncAttributeMaxDynamicSharedMemorySize, SMEM_DYN);
    cudaFuncSetAttribute(mma_gemm<4>, cudaFuncAttributeMaxDynamicSharedMemorySize, SMEM_DYN);

    // ---- weight prep ----
    trans_split<<<dim3(Hd/32,  Hd/32),  256>>>(Wq,   Hd,  wth + WQ_OFF,  wtl + WQ_OFF,  Hd,  0);
    trans_split<<<dim3(Hd/32,  Hd/32),  256>>>(Wk,   Hd,  wth + WK_OFF,  wtl + WK_OFF,  Hd,  0);
    trans_split<<<dim3(Hd/32,  Hd/32),  256>>>(Wv,   Hd,  wth + WV_OFF,  wtl + WV_OFF,  Hd,  0);
    trans_split<<<dim3(Hd/32,  C2H/32), 256>>>(gw1,  Hd,  wth + GW1_OFF, wtl + GW1_OFF, C2H, 0);
    trans_split<<<dim3(Hd/32,  Hd/32),  256>>>(gw2,  Hd,  wth + GW2_OFF, wtl + GW2_OFF, Hd,  0);
    trans_split<<<dim3(Hd/32,  Hd/32),  256>>>(outw, Hd,  wth + OW_OFF,  wtl + OW_OFF,  Hd,  0);
    for (int e = 0; e < Ee; ++e) {
        trans_split<<<dim3(RHd/32, C2H/32), 256>>>(ew1 + (size_t)e*3072*RHd, RHd,
            wth + EW1_OFF + (size_t)e*RHd*C2H, wtl + EW1_OFF + (size_t)e*RHd*C2H, C2H, 0);
        trans_split<<<dim3(Hd/32, RHd/32), 256>>>(ew2 + (size_t)e*RHd*Hd, Hd,
            wth + EW2_OFF, wtl + EW2_OFF, CK6, e*RHd);
    }
    split_arr<<<(Bb*Pp*Hd + 255)/256, 256>>>(proto, phi, plo, Bb*Pp*Hd);

    // ---- anchor folding ----
    anchor_pre<<<dim3(29, Bb), 256>>>(anchor, ew1, gw1, routerW, aux);

    // ---- LN ----
    ln_kernel<<<BT, 256>>>(x, gamma, beta, combined, chi, clo);

    // ---- q, k, v ----
    mma_gemm<0><<<dim3(Hd/128, BT/256), 512, SMEM_DYN>>>(
        chi, clo, C2H, wth + WQ_OFF, wtl + WQ_OFF, Hd,
        q, Hd, nullptr, nullptr, nullptr, nullptr, 0, nullptr, 0, nullptr, nullptr);
    mma_gemm<0><<<dim3(Hd/128, (Bb*Pp)/256), 512, SMEM_DYN>>>(
        phi, plo, Hd, wth + WK_OFF, wtl + WK_OFF, Hd,
        k, Hd, nullptr, nullptr, nullptr, nullptr, 0, nullptr, 0, nullptr, nullptr);
    mma_gemm<0><<<dim3(Hd/128, (Bb*Pp)/256), 512, SMEM_DYN>>>(
        phi, plo, Hd, wth + WV_OFF, wtl + WV_OFF, Hd,
        v, Hd, nullptr, nullptr, nullptr, nullptr, 0, nullptr, 0, nullptr, nullptr);

    // ---- attention ----
    attn4_kernel<<<BT/4, 256>>>(q, k, v, combined, chi, clo);

    // ---- router ----
    router_kernel<<<BT, 128>>>(combined, routerW, routerB, aux, probs);

    // ---- expert up (prob folded) -> h'[BT,6144] ----
    for (int e = 0; e < Ee; ++e) {
        mma_gemm<1><<<dim3(RHd/128, BT/256), 512, SMEM_DYN>>>(
            chi, clo, C2H,
            wth + EW1_OFF + (size_t)e*RHd*C2H, wtl + EW1_OFF + (size_t)e*RHd*C2H, C2H,
            nullptr, CK6, hhi + (size_t)e*RHd, hlo + (size_t)e*RHd,
            eb1 + (size_t)e*RHd, aux + e*8*RHd, RHd, probs, e, nullptr, nullptr);
    }

    // ---- fused expert down ----
    mma_gemm<2><<<dim3(Hd/128, BT/256), 512, SMEM_DYN>>>(
        hhi, hlo, CK6, wth + EW2_OFF, wtl + EW2_OFF, CK6,
        nullptr, Hd, rhi, rlo, eb2, nullptr, 0, probs, 0, nullptr, nullptr);

    // ---- gate MLP ----
    mma_gemm<1><<<dim3(Hd/128, BT/256), 512, SMEM_DYN>>>(
        chi, clo, C2H, wth + GW1_OFF, wtl + GW1_OFF, C2H,
        nullptr, Hd, g1hi, g1lo, gb1, aux + AUX_AG1, Hd, nullptr, 0, nullptr, nullptr);
    mma_gemm<3><<<dim3(Hd/128, BT/256), 512, SMEM_DYN>>>(
        g1hi, g1lo, Hd, wth + GW2_OFF, wtl + GW2_OFF, Hd,
        gate, Hd, nullptr, nullptr, gb2, nullptr, 0, nullptr, 0, nullptr, nullptr);

    // ---- final ----
    mma_gemm<4><<<dim3(Hd/128, BT/256), 512, SMEM_DYN>>>(
        rhi, rlo, Hd, wth + OW_OFF, wtl + OW_OFF, Hd,
        out, Hd, nullptr, nullptr, outb, nullptr, 0, nullptr, 0, gate, x);
}